// round 3
// baseline (speedup 1.0000x reference)
#include <cuda_runtime.h>
#include <cuda_bf16.h>
#include <math.h>

// ---------------------------------------------------------------------------
// Problem constants (fixed by the reference): B=2, S=2048, D=768, H=12, dk=64
// ---------------------------------------------------------------------------
#define B_SZ     2
#define S_LEN    2048
#define D_MODEL  768
#define N_HEADS  12
#define D_K      64
#define D_FF     3072
#define M_ROWS   (B_SZ * S_LEN)           // 4096

// Scratch: one big __device__ array, offsets below (floats)
//   q, k, v, ctx, h1, x1, h2 : 4096*768 each ; ff : 4096*3072
#define SZ_DM   (M_ROWS * D_MODEL)        // 3,145,728
#define SZ_FF   (M_ROWS * D_FF)           // 12,582,912
__device__ float g_scratch[7 * SZ_DM + SZ_FF];

#define OFF_Q    (0 * SZ_DM)
#define OFF_K    (1 * SZ_DM)
#define OFF_V    (2 * SZ_DM)
#define OFF_CTX  (3 * SZ_DM)
#define OFF_H1   (4 * SZ_DM)
#define OFF_X1   (5 * SZ_DM)
#define OFF_H2   (6 * SZ_DM)
#define OFF_FF   (7 * SZ_DM)

// ---------------------------------------------------------------------------
// Generic tiled FP32 GEMM: C[M,N] = A[M,K] @ W[K,N] + bias, epilogue by MODE
//   MODE 0: bias only
//   MODE 1: bias + exact GELU
//   MODE 2: bias + residual add (Res[M,N])
// BM=BN=64, BK=16, 256 threads, each thread 4x4.
// ---------------------------------------------------------------------------
__device__ __forceinline__ float gelu_exact(float x) {
    return 0.5f * x * (1.0f + erff(x * 0.70710678118654752440f));
}

template <int MODE>
__global__ void gemm_kernel(const float* __restrict__ A,
                            const float* __restrict__ W,
                            const float* __restrict__ bias,
                            const float* __restrict__ Res,
                            float* __restrict__ C,
                            int M, int N, int K) {
    __shared__ float As[16][68];   // [k][m], padded (stride 68 -> 16B aligned, low conflict)
    __shared__ float Bs[16][64];   // [k][n]

    const int tid = threadIdx.x;
    const int ty  = tid >> 4;      // 0..15
    const int tx  = tid & 15;      // 0..15
    const int bm  = blockIdx.y * 64;
    const int bn  = blockIdx.x * 64;

    float acc[4][4];
#pragma unroll
    for (int i = 0; i < 4; i++)
#pragma unroll
        for (int j = 0; j < 4; j++) acc[i][j] = 0.0f;

    for (int k0 = 0; k0 < K; k0 += 16) {
        // Load A tile 64x16 (store transposed As[k][m])
#pragma unroll
        for (int t = tid; t < 1024; t += 256) {
            int r = t >> 4, c = t & 15;
            As[c][r] = A[(size_t)(bm + r) * K + (k0 + c)];
        }
        // Load W tile 16x64
#pragma unroll
        for (int t = tid; t < 1024; t += 256) {
            int r = t >> 6, c = t & 63;
            Bs[r][c] = W[(size_t)(k0 + r) * N + (bn + c)];
        }
        __syncthreads();

#pragma unroll
        for (int kk = 0; kk < 16; kk++) {
            float4 a = *(const float4*)&As[kk][ty * 4];
            float4 b = *(const float4*)&Bs[kk][tx * 4];
            acc[0][0] += a.x * b.x; acc[0][1] += a.x * b.y; acc[0][2] += a.x * b.z; acc[0][3] += a.x * b.w;
            acc[1][0] += a.y * b.x; acc[1][1] += a.y * b.y; acc[1][2] += a.y * b.z; acc[1][3] += a.y * b.w;
            acc[2][0] += a.z * b.x; acc[2][1] += a.z * b.y; acc[2][2] += a.z * b.z; acc[2][3] += a.z * b.w;
            acc[3][0] += a.w * b.x; acc[3][1] += a.w * b.y; acc[3][2] += a.w * b.z; acc[3][3] += a.w * b.w;
        }
        __syncthreads();
    }

#pragma unroll
    for (int i = 0; i < 4; i++) {
        int row = bm + ty * 4 + i;
#pragma unroll
        for (int j = 0; j < 4; j++) {
            int col = bn + tx * 4 + j;
            float v = acc[i][j] + bias[col];
            if (MODE == 1) v = gelu_exact(v);
            if (MODE == 2) v += Res[(size_t)row * N + col];
            C[(size_t)row * N + col] = v;
        }
    }
}

// ---------------------------------------------------------------------------
// Flash-style attention. Q/K/V in [B, S, H*Dk] layout (row stride 768).
// Grid: (S/64, B*H). Block: 256 threads. BQ=64 queries, BKV=32 keys per tile.
// Thread (ty,tx) in 16x16 owns q-rows ty*4..+3; score cols tx*2..+1; out cols tx*4..+3.
// ---------------------------------------------------------------------------
__global__ void attn_kernel(const float* __restrict__ Q,
                            const float* __restrict__ K,
                            const float* __restrict__ V,
                            const int* __restrict__ mask,
                            float* __restrict__ O) {
    __shared__ float Qs[64][64];   // [q][d]  (broadcast reads -> no pad needed)
    __shared__ float Ks[32][65];   // [k][d]  padded
    __shared__ float Vs[32][65];   // [k][d]  padded
    __shared__ float Ps[64][33];   // [q][k]  padded
    __shared__ int   Ms[32];

    const int bh = blockIdx.y;
    const int b  = bh / N_HEADS;
    const int h  = bh % N_HEADS;
    const int q0 = blockIdx.x * 64;
    const int tid = threadIdx.x;
    const int ty  = tid >> 4;
    const int tx  = tid & 15;
    const int qr  = ty * 4;

    const float* Qb = Q + (size_t)(b * S_LEN) * D_MODEL + h * D_K;
    const float* Kb = K + (size_t)(b * S_LEN) * D_MODEL + h * D_K;
    const float* Vb = V + (size_t)(b * S_LEN) * D_MODEL + h * D_K;
    const int*   mb = mask + b * S_LEN;

    // Load Q tile
#pragma unroll
    for (int t = tid; t < 64 * 64; t += 256) {
        int r = t >> 6, c = t & 63;
        Qs[r][c] = Qb[(size_t)(q0 + r) * D_MODEL + c];
    }

    float acc[4][4];
    float m_i[4], l_i[4];
#pragma unroll
    for (int i = 0; i < 4; i++) {
        m_i[i] = -1e30f; l_i[i] = 0.0f;
#pragma unroll
        for (int j = 0; j < 4; j++) acc[i][j] = 0.0f;
    }
    const float scale = 0.125f;  // 1/sqrt(64)

    __syncthreads();

    for (int k0 = 0; k0 < S_LEN; k0 += 32) {
        // Load K/V tiles (32 rows x 64 cols each) + mask slice
#pragma unroll
        for (int t = tid; t < 32 * 64; t += 256) {
            int r = t >> 6, c = t & 63;
            Ks[r][c] = Kb[(size_t)(k0 + r) * D_MODEL + c];
            Vs[r][c] = Vb[(size_t)(k0 + r) * D_MODEL + c];
        }
        if (tid < 32) Ms[tid] = mb[k0 + tid];
        __syncthreads();

        // Scores: s[i][j] for rows qr+i, key cols tx*2+j
        float s[4][2];
        s[0][0]=0;s[0][1]=0;s[1][0]=0;s[1][1]=0;s[2][0]=0;s[2][1]=0;s[3][0]=0;s[3][1]=0;
#pragma unroll 16
        for (int d = 0; d < 64; d++) {
            float a0 = Qs[qr + 0][d];
            float a1 = Qs[qr + 1][d];
            float a2 = Qs[qr + 2][d];
            float a3 = Qs[qr + 3][d];
            float b0 = Ks[tx * 2 + 0][d];
            float b1 = Ks[tx * 2 + 1][d];
            s[0][0] += a0 * b0; s[0][1] += a0 * b1;
            s[1][0] += a1 * b0; s[1][1] += a1 * b1;
            s[2][0] += a2 * b0; s[2][1] += a2 * b1;
            s[3][0] += a3 * b0; s[3][1] += a3 * b1;
        }
        // scale + mask
        int mk0 = Ms[tx * 2 + 0];
        int mk1 = Ms[tx * 2 + 1];
#pragma unroll
        for (int i = 0; i < 4; i++) {
            s[i][0] = (mk0 != 0) ? s[i][0] * scale : -1e9f;
            s[i][1] = (mk1 != 0) ? s[i][1] * scale : -1e9f;
        }

        // Online softmax: row max over 32 key cols (16-lane butterfly)
        float p[4][2];
#pragma unroll
        for (int i = 0; i < 4; i++) {
            float mt = fmaxf(s[i][0], s[i][1]);
            mt = fmaxf(mt, __shfl_xor_sync(0xffffffffu, mt, 1));
            mt = fmaxf(mt, __shfl_xor_sync(0xffffffffu, mt, 2));
            mt = fmaxf(mt, __shfl_xor_sync(0xffffffffu, mt, 4));
            mt = fmaxf(mt, __shfl_xor_sync(0xffffffffu, mt, 8));
            float m_new = fmaxf(m_i[i], mt);
            float alpha = __expf(m_i[i] - m_new);
            m_i[i] = m_new;
            p[i][0] = __expf(s[i][0] - m_new);
            p[i][1] = __expf(s[i][1] - m_new);
            float ls = p[i][0] + p[i][1];
            ls += __shfl_xor_sync(0xffffffffu, ls, 1);
            ls += __shfl_xor_sync(0xffffffffu, ls, 2);
            ls += __shfl_xor_sync(0xffffffffu, ls, 4);
            ls += __shfl_xor_sync(0xffffffffu, ls, 8);
            l_i[i] = l_i[i] * alpha + ls;
#pragma unroll
            for (int j = 0; j < 4; j++) acc[i][j] *= alpha;
        }

        // Stage P to shared
#pragma unroll
        for (int i = 0; i < 4; i++) {
            Ps[qr + i][tx * 2 + 0] = p[i][0];
            Ps[qr + i][tx * 2 + 1] = p[i][1];
        }
        __syncthreads();

        // O += P @ V
#pragma unroll 8
        for (int k = 0; k < 32; k++) {
            float a0 = Ps[qr + 0][k];
            float a1 = Ps[qr + 1][k];
            float a2 = Ps[qr + 2][k];
            float a3 = Ps[qr + 3][k];
            float b0 = Vs[k][tx * 4 + 0];
            float b1 = Vs[k][tx * 4 + 1];
            float b2 = Vs[k][tx * 4 + 2];
            float b3 = Vs[k][tx * 4 + 3];
            acc[0][0] += a0 * b0; acc[0][1] += a0 * b1; acc[0][2] += a0 * b2; acc[0][3] += a0 * b3;
            acc[1][0] += a1 * b0; acc[1][1] += a1 * b1; acc[1][2] += a1 * b2; acc[1][3] += a1 * b3;
            acc[2][0] += a2 * b0; acc[2][1] += a2 * b1; acc[2][2] += a2 * b2; acc[2][3] += a2 * b3;
            acc[3][0] += a3 * b0; acc[3][1] += a3 * b1; acc[3][2] += a3 * b2; acc[3][3] += a3 * b3;
        }
        __syncthreads();
    }

    // Finalize + write ctx in [B,S,H*Dk] layout
#pragma unroll
    for (int i = 0; i < 4; i++) {
        float inv_l = 1.0f / l_i[i];
        size_t row = (size_t)(b * S_LEN + q0 + qr + i) * D_MODEL + h * D_K;
#pragma unroll
        for (int j = 0; j < 4; j++) {
            O[row + tx * 4 + j] = acc[i][j] * inv_l;
        }
    }
}

// ---------------------------------------------------------------------------
// LayerNorm: one block per row of 768. 256 threads, 3 elements each.
// ---------------------------------------------------------------------------
__global__ void layernorm_kernel(const float* __restrict__ in,
                                 const float* __restrict__ gamma,
                                 const float* __restrict__ beta,
                                 float* __restrict__ out) {
    const int row = blockIdx.x;
    const int tid = threadIdx.x;
    const float* x = in + (size_t)row * D_MODEL;
    float* y = out + (size_t)row * D_MODEL;

    float v[3];
    float s = 0.0f, sq = 0.0f;
#pragma unroll
    for (int r = 0; r < 3; r++) {
        v[r] = x[tid + r * 256];
        s  += v[r];
        sq += v[r] * v[r];
    }
    // warp reduce
#pragma unroll
    for (int off = 16; off > 0; off >>= 1) {
        s  += __shfl_xor_sync(0xffffffffu, s,  off);
        sq += __shfl_xor_sync(0xffffffffu, sq, off);
    }
    __shared__ float ss[8], ssq[8];
    int wid = tid >> 5, lane = tid & 31;
    if (lane == 0) { ss[wid] = s; ssq[wid] = sq; }
    __syncthreads();
    s = 0.0f; sq = 0.0f;
#pragma unroll
    for (int w = 0; w < 8; w++) { s += ss[w]; sq += ssq[w]; }

    const float inv_n = 1.0f / (float)D_MODEL;
    float mean = s * inv_n;
    float var  = sq * inv_n - mean * mean;
    float rstd = rsqrtf(var + 1e-5f);
#pragma unroll
    for (int r = 0; r < 3; r++) {
        int c = tid + r * 256;
        y[c] = (v[r] - mean) * rstd * gamma[c] + beta[c];
    }
}

// ---------------------------------------------------------------------------
// Launch
// ---------------------------------------------------------------------------
extern "C" void kernel_launch(void* const* d_in, const int* in_sizes, int n_in,
                              void* d_out, int out_size) {
    const float* x    = (const float*)d_in[0];
    const int*   mask = (const int*)  d_in[1];
    const float* wq = (const float*)d_in[2];
    const float* bq = (const float*)d_in[3];
    const float* wk = (const float*)d_in[4];
    const float* bk = (const float*)d_in[5];
    const float* wv = (const float*)d_in[6];
    const float* bv = (const float*)d_in[7];
    const float* wo = (const float*)d_in[8];
    const float* bo = (const float*)d_in[9];
    const float* w1 = (const float*)d_in[10];
    const float* b1 = (const float*)d_in[11];
    const float* w2 = (const float*)d_in[12];
    const float* b2 = (const float*)d_in[13];
    const float* g1 = (const float*)d_in[14];
    const float* be1= (const float*)d_in[15];
    const float* g2 = (const float*)d_in[16];
    const float* be2= (const float*)d_in[17];
    float* out = (float*)d_out;

    void* sptr = nullptr;
    cudaGetSymbolAddress(&sptr, g_scratch);
    float* S = (float*)sptr;
    float* q_b  = S + OFF_Q;
    float* k_b  = S + OFF_K;
    float* v_b  = S + OFF_V;
    float* ctx  = S + OFF_CTX;
    float* h1   = S + OFF_H1;
    float* x1   = S + OFF_X1;
    float* h2   = S + OFF_H2;
    float* ff   = S + OFF_FF;

    dim3 blk(256);
    dim3 grid_dm(D_MODEL / 64, M_ROWS / 64);   // (12, 64)
    dim3 grid_ff(D_FF / 64,   M_ROWS / 64);    // (48, 64)

    // QKV projections
    gemm_kernel<0><<<grid_dm, blk>>>(x, wq, bq, nullptr, q_b, M_ROWS, D_MODEL, D_MODEL);
    gemm_kernel<0><<<grid_dm, blk>>>(x, wk, bk, nullptr, k_b, M_ROWS, D_MODEL, D_MODEL);
    gemm_kernel<0><<<grid_dm, blk>>>(x, wv, bv, nullptr, v_b, M_ROWS, D_MODEL, D_MODEL);

    // Attention
    dim3 agrid(S_LEN / 64, B_SZ * N_HEADS);    // (32, 24)
    attn_kernel<<<agrid, blk>>>(q_b, k_b, v_b, mask, ctx);

    // Output projection + residual, then LN1
    gemm_kernel<2><<<grid_dm, blk>>>(ctx, wo, bo, x, h1, M_ROWS, D_MODEL, D_MODEL);
    layernorm_kernel<<<M_ROWS, blk>>>(h1, g1, be1, x1);

    // FFN
    gemm_kernel<1><<<grid_ff, blk>>>(x1, w1, b1, nullptr, ff, M_ROWS, D_FF, D_MODEL);
    gemm_kernel<2><<<grid_dm, blk>>>(ff, w2, b2, x1, h2, M_ROWS, D_MODEL, D_FF);
    layernorm_kernel<<<M_ROWS, blk>>>(h2, g2, be2, out);
}

// round 4
// speedup vs baseline: 2.9888x; 2.9888x over previous
#include <cuda_runtime.h>
#include <math.h>

// ---------------------------------------------------------------------------
// B=2, S=2048, D=768, H=12, dk=64, FF=3072
// ---------------------------------------------------------------------------
#define B_SZ     2
#define S_LEN    2048
#define D_MODEL  768
#define N_HEADS  12
#define D_K      64
#define D_FF     3072
#define M_ROWS   (B_SZ * S_LEN)           // 4096

#define SZ_DM   (M_ROWS * D_MODEL)
#define SZ_FF   (M_ROWS * D_FF)
__device__ float g_scratch[7 * SZ_DM + SZ_FF];

#define OFF_Q    (0 * SZ_DM)
#define OFF_K    (1 * SZ_DM)
#define OFF_V    (2 * SZ_DM)
#define OFF_CTX  (3 * SZ_DM)
#define OFF_H1   (4 * SZ_DM)
#define OFF_X1   (5 * SZ_DM)
#define OFF_H2   (6 * SZ_DM)
#define OFF_FF   (7 * SZ_DM)

// ---------------------------------------------------------------------------
// tf32 helpers + m16n8k8 mma
// ---------------------------------------------------------------------------
__device__ __forceinline__ unsigned f2tf(float x) {
    unsigned u;
    asm("cvt.rna.tf32.f32 %0, %1;" : "=r"(u) : "f"(x));
    return u;
}
__device__ __forceinline__ uint4 f2tf4(float4 v) {
    uint4 u;
    u.x = f2tf(v.x); u.y = f2tf(v.y); u.z = f2tf(v.z); u.w = f2tf(v.w);
    return u;
}
__device__ __forceinline__ void mma8(float c[4], const unsigned a[4], const unsigned b[2]) {
    asm volatile(
        "mma.sync.aligned.m16n8k8.row.col.f32.tf32.tf32.f32 "
        "{%0,%1,%2,%3}, {%4,%5,%6,%7}, {%8,%9}, {%0,%1,%2,%3};\n"
        : "+f"(c[0]), "+f"(c[1]), "+f"(c[2]), "+f"(c[3])
        : "r"(a[0]), "r"(a[1]), "r"(a[2]), "r"(a[3]), "r"(b[0]), "r"(b[1]));
}

__device__ __forceinline__ float gelu_exact(float x) {
    return 0.5f * x * (1.0f + erff(x * 0.70710678118654752440f));
}

// ---------------------------------------------------------------------------
// Tensor-core GEMM: C[M,N] = A[M,K] @ W[K,N] + bias (+ gelu / + residual)
// Block tile 128x128, BK=16, 256 threads (8 warps, 4m x 2n), warp tile 32x64.
// Double-buffered smem, register prefetch, one sync per K-tile.
//   A smem: [m][k], stride 20  -> conflict-free A-frag loads
//   B smem: [k][n], stride 136 -> conflict-free B-frag loads
// ---------------------------------------------------------------------------
template <int MODE>   // 0: bias, 1: bias+gelu, 2: bias+residual
__global__ void __launch_bounds__(256)
gemm_tc(const float* __restrict__ A, const float* __restrict__ W,
        const float* __restrict__ bias, const float* __restrict__ Res,
        float* __restrict__ C, int M, int N, int K) {
    __shared__ unsigned As[2][128][20];
    __shared__ unsigned Bs[2][16][136];

    const int tid  = threadIdx.x;
    const int wid  = tid >> 5;
    const int lane = tid & 31;
    const int g    = lane >> 2;      // 0..7
    const int t4   = lane & 3;       // 0..3
    const int wm   = wid & 3;        // 0..3
    const int wn   = wid >> 2;       // 0..1
    const int bm   = blockIdx.y * 128;
    const int bn   = blockIdx.x * 128;

    // per-thread load coords
    const int am = tid >> 2;         // A: rows am, am+64 ; cols kq*4..+3
    const int akq = tid & 3;
    const int bkr = tid >> 5;        // B: rows bkr, bkr+8 ; cols nq*4..+3
    const int bnq = tid & 31;

    float c[2][8][4];
#pragma unroll
    for (int mt = 0; mt < 2; mt++)
#pragma unroll
        for (int nt = 0; nt < 8; nt++)
#pragma unroll
            for (int i = 0; i < 4; i++) c[mt][nt][i] = 0.0f;

    // preload tile 0
    {
        uint4 ra0 = f2tf4(*(const float4*)(A + (size_t)(bm + am) * K + akq * 4));
        uint4 ra1 = f2tf4(*(const float4*)(A + (size_t)(bm + am + 64) * K + akq * 4));
        uint4 rb0 = f2tf4(*(const float4*)(W + (size_t)(bkr) * N + bn + bnq * 4));
        uint4 rb1 = f2tf4(*(const float4*)(W + (size_t)(bkr + 8) * N + bn + bnq * 4));
        *(uint4*)&As[0][am][akq * 4]      = ra0;
        *(uint4*)&As[0][am + 64][akq * 4] = ra1;
        *(uint4*)&Bs[0][bkr][bnq * 4]     = rb0;
        *(uint4*)&Bs[0][bkr + 8][bnq * 4] = rb1;
    }
    __syncthreads();

    int buf = 0;
    for (int k0 = 0; k0 < K; k0 += 16) {
        const bool has_next = (k0 + 16) < K;
        uint4 ra0, ra1, rb0, rb1;
        if (has_next) {
            int kn = k0 + 16;
            ra0 = f2tf4(*(const float4*)(A + (size_t)(bm + am) * K + kn + akq * 4));
            ra1 = f2tf4(*(const float4*)(A + (size_t)(bm + am + 64) * K + kn + akq * 4));
            rb0 = f2tf4(*(const float4*)(W + (size_t)(kn + bkr) * N + bn + bnq * 4));
            rb1 = f2tf4(*(const float4*)(W + (size_t)(kn + bkr + 8) * N + bn + bnq * 4));
        }

#pragma unroll
        for (int kk = 0; kk < 16; kk += 8) {
            unsigned a[2][4], b[8][2];
#pragma unroll
            for (int mt = 0; mt < 2; mt++) {
                int rb = wm * 32 + mt * 16;
                a[mt][0] = As[buf][rb + g][kk + t4];
                a[mt][1] = As[buf][rb + g + 8][kk + t4];
                a[mt][2] = As[buf][rb + g][kk + t4 + 4];
                a[mt][3] = As[buf][rb + g + 8][kk + t4 + 4];
            }
#pragma unroll
            for (int nt = 0; nt < 8; nt++) {
                int cb = wn * 64 + nt * 8;
                b[nt][0] = Bs[buf][kk + t4][cb + g];
                b[nt][1] = Bs[buf][kk + t4 + 4][cb + g];
            }
#pragma unroll
            for (int mt = 0; mt < 2; mt++)
#pragma unroll
                for (int nt = 0; nt < 8; nt++)
                    mma8(c[mt][nt], a[mt], b[nt]);
        }

        if (has_next) {
            int nxt = buf ^ 1;
            *(uint4*)&As[nxt][am][akq * 4]      = ra0;
            *(uint4*)&As[nxt][am + 64][akq * 4] = ra1;
            *(uint4*)&Bs[nxt][bkr][bnq * 4]     = rb0;
            *(uint4*)&Bs[nxt][bkr + 8][bnq * 4] = rb1;
        }
        __syncthreads();
        buf ^= 1;
    }

    // epilogue
#pragma unroll
    for (int mt = 0; mt < 2; mt++) {
        int r0 = bm + wm * 32 + mt * 16 + g;
        int r1 = r0 + 8;
#pragma unroll
        for (int nt = 0; nt < 8; nt++) {
            int col = bn + wn * 64 + nt * 8 + t4 * 2;
            float bb0 = bias[col], bb1 = bias[col + 1];
            float v00 = c[mt][nt][0] + bb0;
            float v01 = c[mt][nt][1] + bb1;
            float v10 = c[mt][nt][2] + bb0;
            float v11 = c[mt][nt][3] + bb1;
            if (MODE == 1) {
                v00 = gelu_exact(v00); v01 = gelu_exact(v01);
                v10 = gelu_exact(v10); v11 = gelu_exact(v11);
            }
            if (MODE == 2) {
                float2 r0v = *(const float2*)(Res + (size_t)r0 * N + col);
                float2 r1v = *(const float2*)(Res + (size_t)r1 * N + col);
                v00 += r0v.x; v01 += r0v.y; v10 += r1v.x; v11 += r1v.y;
            }
            float2 o0 = {v00, v01}, o1 = {v10, v11};
            *(float2*)(C + (size_t)r0 * N + col) = o0;
            *(float2*)(C + (size_t)r1 * N + col) = o1;
        }
    }
}

// ---------------------------------------------------------------------------
// Tensor-core flash attention. BQ=64, BKV=32, 256 threads (8 warps: 2m x 4n).
// QK^T and PV via m16n8k8 tf32 mma; online softmax with per-row state in smem.
// ---------------------------------------------------------------------------
__global__ void __launch_bounds__(256)
attn_tc(const float* __restrict__ Q, const float* __restrict__ K,
        const float* __restrict__ V, const int* __restrict__ mask,
        float* __restrict__ O) {
    __shared__ unsigned Qs[64][68];   // [q][d]   tf32
    __shared__ unsigned Ks[32][68];   // [kv][d]  tf32
    __shared__ unsigned Vs[32][72];   // [kv][d]  tf32
    __shared__ float    Ss[64][40];   // [q][kv]  scores, then P (tf32 bits)
    __shared__ float    m_sm[64], l_sm[64], alpha_sm[64];
    __shared__ int      Ms[32];

    const int bh  = blockIdx.y;
    const int b   = bh / N_HEADS;
    const int h   = bh % N_HEADS;
    const int q0  = blockIdx.x * 64;
    const int tid = threadIdx.x;
    const int wid = tid >> 5;
    const int lane = tid & 31;
    const int g   = lane >> 2;
    const int t4  = lane & 3;
    const int wm  = wid & 1;          // 0..1  (32 q-rows each)
    const int wn  = wid >> 1;         // 0..3

    const float* Qb = Q + (size_t)b * S_LEN * D_MODEL + h * D_K;
    const float* Kb = K + (size_t)b * S_LEN * D_MODEL + h * D_K;
    const float* Vb = V + (size_t)b * S_LEN * D_MODEL + h * D_K;
    const int*   mb = mask + b * S_LEN;

    // load Q tile (tf32)
#pragma unroll
    for (int i = 0; i < 4; i++) {
        int f = tid + i * 256;
        int r = f >> 4, dq = f & 15;
        float4 v = *(const float4*)(Qb + (size_t)(q0 + r) * D_MODEL + dq * 4);
        *(uint4*)&Qs[r][dq * 4] = f2tf4(v);
    }
    if (tid < 64) { m_sm[tid] = -1e30f; l_sm[tid] = 0.0f; }

    float o[2][2][4];
#pragma unroll
    for (int mt = 0; mt < 2; mt++)
#pragma unroll
        for (int nt = 0; nt < 2; nt++)
#pragma unroll
            for (int i = 0; i < 4; i++) o[mt][nt][i] = 0.0f;

    __syncthreads();

    for (int k0 = 0; k0 < S_LEN; k0 += 32) {
        // load K/V tiles (tf32) + mask slice
#pragma unroll
        for (int i = 0; i < 2; i++) {
            int f = tid + i * 256;
            int r = f >> 4, dq = f & 15;
            float4 kv = *(const float4*)(Kb + (size_t)(k0 + r) * D_MODEL + dq * 4);
            *(uint4*)&Ks[r][dq * 4] = f2tf4(kv);
            float4 vv = *(const float4*)(Vb + (size_t)(k0 + r) * D_MODEL + dq * 4);
            *(uint4*)&Vs[r][dq * 4] = f2tf4(vv);
        }
        if (tid < 32) Ms[tid] = mb[k0 + tid];
        __syncthreads();

        // S = Q @ K^T   (each warp: 32 q-rows x 8 kv-cols)
        float s[2][4];
#pragma unroll
        for (int mt = 0; mt < 2; mt++)
#pragma unroll
            for (int i = 0; i < 4; i++) s[mt][i] = 0.0f;

#pragma unroll
        for (int kk = 0; kk < 64; kk += 8) {
            unsigned a[2][4], bf[2];
#pragma unroll
            for (int mt = 0; mt < 2; mt++) {
                int rb = wm * 32 + mt * 16;
                a[mt][0] = Qs[rb + g][kk + t4];
                a[mt][1] = Qs[rb + g + 8][kk + t4];
                a[mt][2] = Qs[rb + g][kk + t4 + 4];
                a[mt][3] = Qs[rb + g + 8][kk + t4 + 4];
            }
            int cb = wn * 8;
            bf[0] = Ks[cb + g][kk + t4];
            bf[1] = Ks[cb + g][kk + t4 + 4];
#pragma unroll
            for (int mt = 0; mt < 2; mt++) mma8(s[mt], a[mt], bf);
        }
        // stage S to smem
#pragma unroll
        for (int mt = 0; mt < 2; mt++) {
            int rb = wm * 32 + mt * 16;
            int cc = wn * 8 + t4 * 2;
            float2 s0 = {s[mt][0], s[mt][1]};
            float2 s1 = {s[mt][2], s[mt][3]};
            *(float2*)&Ss[rb + g][cc]     = s0;
            *(float2*)&Ss[rb + g + 8][cc] = s1;
        }
        __syncthreads();

        // online softmax: 4 threads per row, 8 cols each
        {
            int row = tid >> 2, qq = tid & 3;
            float buf[8];
            float mx = -1e30f;
#pragma unroll
            for (int j = 0; j < 8; j++) {
                int cc = qq * 8 + j;
                float sv = Ss[row][cc];
                sv = (Ms[cc] != 0) ? sv * 0.125f : -1e9f;
                buf[j] = sv;
                mx = fmaxf(mx, sv);
            }
            mx = fmaxf(mx, __shfl_xor_sync(0xffffffffu, mx, 1));
            mx = fmaxf(mx, __shfl_xor_sync(0xffffffffu, mx, 2));
            float m_old = m_sm[row];
            float m_new = fmaxf(m_old, mx);
            float alpha = __expf(m_old - m_new);
            float ps = 0.0f;
#pragma unroll
            for (int j = 0; j < 8; j++) {
                float p = __expf(buf[j] - m_new);
                ps += p;
                Ss[row][qq * 8 + j] = __uint_as_float(f2tf(p));
            }
            ps += __shfl_xor_sync(0xffffffffu, ps, 1);
            ps += __shfl_xor_sync(0xffffffffu, ps, 2);
            if (qq == 0) {
                m_sm[row] = m_new;
                alpha_sm[row] = alpha;
                l_sm[row] = l_sm[row] * alpha + ps;
            }
        }
        __syncthreads();

        // rescale O by alpha, then O += P @ V
#pragma unroll
        for (int mt = 0; mt < 2; mt++) {
            int rb = wm * 32 + mt * 16;
            float af0 = alpha_sm[rb + g];
            float af1 = alpha_sm[rb + g + 8];
#pragma unroll
            for (int nt = 0; nt < 2; nt++) {
                o[mt][nt][0] *= af0; o[mt][nt][1] *= af0;
                o[mt][nt][2] *= af1; o[mt][nt][3] *= af1;
            }
        }
#pragma unroll
        for (int kk = 0; kk < 32; kk += 8) {
            unsigned a[2][4], bf[2][2];
#pragma unroll
            for (int mt = 0; mt < 2; mt++) {
                int rb = wm * 32 + mt * 16;
                a[mt][0] = __float_as_uint(Ss[rb + g][kk + t4]);
                a[mt][1] = __float_as_uint(Ss[rb + g + 8][kk + t4]);
                a[mt][2] = __float_as_uint(Ss[rb + g][kk + t4 + 4]);
                a[mt][3] = __float_as_uint(Ss[rb + g + 8][kk + t4 + 4]);
            }
#pragma unroll
            for (int nt = 0; nt < 2; nt++) {
                int cb = wn * 16 + nt * 8;
                bf[nt][0] = Vs[kk + t4][cb + g];
                bf[nt][1] = Vs[kk + t4 + 4][cb + g];
            }
#pragma unroll
            for (int mt = 0; mt < 2; mt++)
#pragma unroll
                for (int nt = 0; nt < 2; nt++)
                    mma8(o[mt][nt], a[mt], bf[nt]);
        }
        __syncthreads();   // protect Ks/Vs/Ss before next tile
    }

    // finalize: O / l, write ctx [B,S,H*dk]
#pragma unroll
    for (int mt = 0; mt < 2; mt++) {
        int r0 = wm * 32 + mt * 16 + g;
        int r1 = r0 + 8;
        float il0 = 1.0f / l_sm[r0];
        float il1 = 1.0f / l_sm[r1];
        size_t gr0 = (size_t)(b * S_LEN + q0 + r0) * D_MODEL + h * D_K;
        size_t gr1 = (size_t)(b * S_LEN + q0 + r1) * D_MODEL + h * D_K;
#pragma unroll
        for (int nt = 0; nt < 2; nt++) {
            int col = wn * 16 + nt * 8 + t4 * 2;
            float2 o0 = {o[mt][nt][0] * il0, o[mt][nt][1] * il0};
            float2 o1 = {o[mt][nt][2] * il1, o[mt][nt][3] * il1};
            *(float2*)(O + gr0 + col) = o0;
            *(float2*)(O + gr1 + col) = o1;
        }
    }
}

// ---------------------------------------------------------------------------
// LayerNorm: one block per row of 768, 256 threads.
// ---------------------------------------------------------------------------
__global__ void layernorm_kernel(const float* __restrict__ in,
                                 const float* __restrict__ gamma,
                                 const float* __restrict__ beta,
                                 float* __restrict__ out) {
    const int row = blockIdx.x;
    const int tid = threadIdx.x;
    const float* x = in + (size_t)row * D_MODEL;
    float* y = out + (size_t)row * D_MODEL;

    float v[3];
    float s = 0.0f, sq = 0.0f;
#pragma unroll
    for (int r = 0; r < 3; r++) {
        v[r] = x[tid + r * 256];
        s  += v[r];
        sq += v[r] * v[r];
    }
#pragma unroll
    for (int off = 16; off > 0; off >>= 1) {
        s  += __shfl_xor_sync(0xffffffffu, s,  off);
        sq += __shfl_xor_sync(0xffffffffu, sq, off);
    }
    __shared__ float ss[8], ssq[8];
    int wid = tid >> 5, lane = tid & 31;
    if (lane == 0) { ss[wid] = s; ssq[wid] = sq; }
    __syncthreads();
    s = 0.0f; sq = 0.0f;
#pragma unroll
    for (int w = 0; w < 8; w++) { s += ss[w]; sq += ssq[w]; }

    const float inv_n = 1.0f / (float)D_MODEL;
    float mean = s * inv_n;
    float var  = sq * inv_n - mean * mean;
    float rstd = rsqrtf(var + 1e-5f);
#pragma unroll
    for (int r = 0; r < 3; r++) {
        int c = tid + r * 256;
        y[c] = (v[r] - mean) * rstd * gamma[c] + beta[c];
    }
}

// ---------------------------------------------------------------------------
// Launch
// ---------------------------------------------------------------------------
extern "C" void kernel_launch(void* const* d_in, const int* in_sizes, int n_in,
                              void* d_out, int out_size) {
    const float* x    = (const float*)d_in[0];
    const int*   mask = (const int*)  d_in[1];
    const float* wq = (const float*)d_in[2];
    const float* bq = (const float*)d_in[3];
    const float* wk = (const float*)d_in[4];
    const float* bk = (const float*)d_in[5];
    const float* wv = (const float*)d_in[6];
    const float* bv = (const float*)d_in[7];
    const float* wo = (const float*)d_in[8];
    const float* bo = (const float*)d_in[9];
    const float* w1 = (const float*)d_in[10];
    const float* b1 = (const float*)d_in[11];
    const float* w2 = (const float*)d_in[12];
    const float* b2 = (const float*)d_in[13];
    const float* g1 = (const float*)d_in[14];
    const float* be1= (const float*)d_in[15];
    const float* g2 = (const float*)d_in[16];
    const float* be2= (const float*)d_in[17];
    float* out = (float*)d_out;

    void* sptr = nullptr;
    cudaGetSymbolAddress(&sptr, g_scratch);
    float* S = (float*)sptr;
    float* q_b = S + OFF_Q;
    float* k_b = S + OFF_K;
    float* v_b = S + OFF_V;
    float* ctx = S + OFF_CTX;
    float* h1  = S + OFF_H1;
    float* x1  = S + OFF_X1;
    float* h2  = S + OFF_H2;
    float* ff  = S + OFF_FF;

    dim3 blk(256);
    dim3 grid_dm(D_MODEL / 128, M_ROWS / 128);   // (6, 32)
    dim3 grid_ff(D_FF / 128,   M_ROWS / 128);    // (24, 32)

    gemm_tc<0><<<grid_dm, blk>>>(x, wq, bq, nullptr, q_b, M_ROWS, D_MODEL, D_MODEL);
    gemm_tc<0><<<grid_dm, blk>>>(x, wk, bk, nullptr, k_b, M_ROWS, D_MODEL, D_MODEL);
    gemm_tc<0><<<grid_dm, blk>>>(x, wv, bv, nullptr, v_b, M_ROWS, D_MODEL, D_MODEL);

    dim3 agrid(S_LEN / 64, B_SZ * N_HEADS);      // (32, 24)
    attn_tc<<<agrid, blk>>>(q_b, k_b, v_b, mask, ctx);

    gemm_tc<2><<<grid_dm, blk>>>(ctx, wo, bo, x, h1, M_ROWS, D_MODEL, D_MODEL);
    layernorm_kernel<<<M_ROWS, blk>>>(h1, g1, be1, x1);

    gemm_tc<1><<<grid_ff, blk>>>(x1, w1, b1, nullptr, ff, M_ROWS, D_FF, D_MODEL);
    gemm_tc<2><<<grid_dm, blk>>>(ff, w2, b2, x1, h2, M_ROWS, D_MODEL, D_FF);
    layernorm_kernel<<<M_ROWS, blk>>>(h2, g2, be2, out);
}

// round 6
// speedup vs baseline: 3.2379x; 1.0834x over previous
#include <cuda_runtime.h>
#include <math.h>

// ---------------------------------------------------------------------------
// B=2, S=2048, D=768, H=12, dk=64, FF=3072
// ---------------------------------------------------------------------------
#define B_SZ     2
#define S_LEN    2048
#define D_MODEL  768
#define N_HEADS  12
#define D_K      64
#define D_FF     3072
#define M_ROWS   (B_SZ * S_LEN)           // 4096

#define SZ_DM   (M_ROWS * D_MODEL)
#define SZ_FF   (M_ROWS * D_FF)
__device__ float g_scratch[7 * SZ_DM + SZ_FF];

#define OFF_Q    (0 * SZ_DM)
#define OFF_K    (1 * SZ_DM)
#define OFF_V    (2 * SZ_DM)
#define OFF_CTX  (3 * SZ_DM)
#define OFF_H1   (4 * SZ_DM)
#define OFF_X1   (5 * SZ_DM)
#define OFF_H2   (6 * SZ_DM)
#define OFF_FF   (7 * SZ_DM)

// ---------------------------------------------------------------------------
// tf32 helpers + m16n8k8 mma
// ---------------------------------------------------------------------------
__device__ __forceinline__ unsigned f2tf(float x) {
    unsigned u;
    asm("cvt.rna.tf32.f32 %0, %1;" : "=r"(u) : "f"(x));
    return u;
}
__device__ __forceinline__ uint4 f2tf4(float4 v) {
    uint4 u;
    u.x = f2tf(v.x); u.y = f2tf(v.y); u.z = f2tf(v.z); u.w = f2tf(v.w);
    return u;
}
__device__ __forceinline__ void mma8(float c[4], const unsigned a[4], const unsigned b[2]) {
    asm volatile(
        "mma.sync.aligned.m16n8k8.row.col.f32.tf32.tf32.f32 "
        "{%0,%1,%2,%3}, {%4,%5,%6,%7}, {%8,%9}, {%0,%1,%2,%3};\n"
        : "+f"(c[0]), "+f"(c[1]), "+f"(c[2]), "+f"(c[3])
        : "r"(a[0]), "r"(a[1]), "r"(a[2]), "r"(a[3]), "r"(b[0]), "r"(b[1]));
}

__device__ __forceinline__ float gelu_exact(float x) {
    return 0.5f * x * (1.0f + erff(x * 0.70710678118654752440f));
}

// ---------------------------------------------------------------------------
// GEMM body: C[M,N] = A[M,K] @ W[K,N] + bias (+gelu / +residual)
// Block tile 128x128, BK=16, 256 threads (8 warps, 4m x 2n), warp tile 32x64.
// A smem: [m][k-interleaved], pitch 20 -> A-frags via LDS.64
// B smem: [k][n], pitch 136 -> conflict-free B-frag LDS.32
// Double-buffered, register prefetch, one sync per K-tile.
// ---------------------------------------------------------------------------
__device__ __forceinline__ void storeA(unsigned (*As)[20], int am, int akq, uint4 w) {
    unsigned* p = &As[am][(akq >> 1) * 8 + (akq & 1)];
    p[0] = w.x; p[2] = w.y; p[4] = w.z; p[6] = w.w;
}

template <int MODE>   // 0: bias, 1: bias+gelu, 2: bias+residual
__device__ __forceinline__ void gemm_body(
        const float* __restrict__ A, const float* __restrict__ W,
        const float* __restrict__ bias, const float* __restrict__ Res,
        float* __restrict__ C, int M, int N, int K, int bxi, int byi) {
    __shared__ unsigned As[2][128][20];
    __shared__ unsigned Bs[2][16][136];

    const int tid  = threadIdx.x;
    const int wid  = tid >> 5;
    const int lane = tid & 31;
    const int g    = lane >> 2;
    const int t4   = lane & 3;
    const int wm   = wid & 3;
    const int wn   = wid >> 2;
    const int bm   = byi * 128;
    const int bn   = bxi * 128;

    const int am  = tid >> 2;
    const int akq = tid & 3;
    const int bkr = tid >> 5;
    const int bnq = tid & 31;

    float c[2][8][4];
#pragma unroll
    for (int mt = 0; mt < 2; mt++)
#pragma unroll
        for (int nt = 0; nt < 8; nt++)
#pragma unroll
            for (int i = 0; i < 4; i++) c[mt][nt][i] = 0.0f;

    // preload tile 0
    {
        uint4 ra0 = f2tf4(*(const float4*)(A + (size_t)(bm + am) * K + akq * 4));
        uint4 ra1 = f2tf4(*(const float4*)(A + (size_t)(bm + am + 64) * K + akq * 4));
        uint4 rb0 = f2tf4(*(const float4*)(W + (size_t)(bkr) * N + bn + bnq * 4));
        uint4 rb1 = f2tf4(*(const float4*)(W + (size_t)(bkr + 8) * N + bn + bnq * 4));
        storeA(As[0], am, akq, ra0);
        storeA(As[0], am + 64, akq, ra1);
        *(uint4*)&Bs[0][bkr][bnq * 4]     = rb0;
        *(uint4*)&Bs[0][bkr + 8][bnq * 4] = rb1;
    }
    __syncthreads();

    int buf = 0;
    for (int k0 = 0; k0 < K; k0 += 16) {
        const bool has_next = (k0 + 16) < K;
        uint4 ra0, ra1, rb0, rb1;
        if (has_next) {
            int kn = k0 + 16;
            ra0 = f2tf4(*(const float4*)(A + (size_t)(bm + am) * K + kn + akq * 4));
            ra1 = f2tf4(*(const float4*)(A + (size_t)(bm + am + 64) * K + kn + akq * 4));
            rb0 = f2tf4(*(const float4*)(W + (size_t)(kn + bkr) * N + bn + bnq * 4));
            rb1 = f2tf4(*(const float4*)(W + (size_t)(kn + bkr + 8) * N + bn + bnq * 4));
        }

#pragma unroll
        for (int kb = 0; kb < 2; kb++) {
            const int kk = kb * 8;
            unsigned a[2][4], b[8][2];
#pragma unroll
            for (int mt = 0; mt < 2; mt++) {
                const unsigned* r0 = &As[buf][wm * 32 + mt * 16 + g][kb * 8 + 2 * t4];
                uint2 lo = *(const uint2*)r0;
                uint2 hi = *(const uint2*)(r0 + 8 * 20);
                a[mt][0] = lo.x; a[mt][1] = hi.x; a[mt][2] = lo.y; a[mt][3] = hi.y;
            }
#pragma unroll
            for (int nt = 0; nt < 8; nt++) {
                int cb = wn * 64 + nt * 8;
                b[nt][0] = Bs[buf][kk + t4][cb + g];
                b[nt][1] = Bs[buf][kk + t4 + 4][cb + g];
            }
#pragma unroll
            for (int mt = 0; mt < 2; mt++)
#pragma unroll
                for (int nt = 0; nt < 8; nt++)
                    mma8(c[mt][nt], a[mt], b[nt]);
        }

        if (has_next) {
            int nxt = buf ^ 1;
            storeA(As[nxt], am, akq, ra0);
            storeA(As[nxt], am + 64, akq, ra1);
            *(uint4*)&Bs[nxt][bkr][bnq * 4]     = rb0;
            *(uint4*)&Bs[nxt][bkr + 8][bnq * 4] = rb1;
        }
        __syncthreads();
        buf ^= 1;
    }

    // epilogue
#pragma unroll
    for (int mt = 0; mt < 2; mt++) {
        int r0 = bm + wm * 32 + mt * 16 + g;
        int r1 = r0 + 8;
#pragma unroll
        for (int nt = 0; nt < 8; nt++) {
            int col = bn + wn * 64 + nt * 8 + t4 * 2;
            float bb0 = bias[col], bb1 = bias[col + 1];
            float v00 = c[mt][nt][0] + bb0;
            float v01 = c[mt][nt][1] + bb1;
            float v10 = c[mt][nt][2] + bb0;
            float v11 = c[mt][nt][3] + bb1;
            if (MODE == 1) {
                v00 = gelu_exact(v00); v01 = gelu_exact(v01);
                v10 = gelu_exact(v10); v11 = gelu_exact(v11);
            }
            if (MODE == 2) {
                float2 r0v = *(const float2*)(Res + (size_t)r0 * N + col);
                float2 r1v = *(const float2*)(Res + (size_t)r1 * N + col);
                v00 += r0v.x; v01 += r0v.y; v10 += r1v.x; v11 += r1v.y;
            }
            float2 o0 = {v00, v01}, o1 = {v10, v11};
            *(float2*)(C + (size_t)r0 * N + col) = o0;
            *(float2*)(C + (size_t)r1 * N + col) = o1;
        }
    }
}

template <int MODE>
__global__ void __launch_bounds__(256)
gemm_tc(const float* __restrict__ A, const float* __restrict__ W,
        const float* __restrict__ bias, const float* __restrict__ Res,
        float* __restrict__ C, int M, int N, int K) {
    gemm_body<MODE>(A, W, bias, Res, C, M, N, K, blockIdx.x, blockIdx.y);
}

// Fused QKV: grid.x = 18 (6 col-blocks per projection), selects W/bias/output.
__global__ void __launch_bounds__(256)
gemm_qkv(const float* __restrict__ A,
         const float* __restrict__ Wq, const float* __restrict__ Wk, const float* __restrict__ Wv,
         const float* __restrict__ bq, const float* __restrict__ bk, const float* __restrict__ bv,
         float* __restrict__ Oq, float* __restrict__ Ok, float* __restrict__ Ov,
         int M, int K) {
    int sel = blockIdx.x / 6;
    int bx  = blockIdx.x - sel * 6;
    const float* W    = (sel == 0) ? Wq : (sel == 1) ? Wk : Wv;
    const float* bias = (sel == 0) ? bq : (sel == 1) ? bk : bv;
    float*       C    = (sel == 0) ? Oq : (sel == 1) ? Ok : Ov;
    gemm_body<0>(A, W, bias, nullptr, C, M, D_MODEL, K, bx, blockIdx.y);
}

// ---------------------------------------------------------------------------
// Flash attention v2: BQ=128 (16 q-rows per warp, 8 warps), BKV=64.
// Q fragments in registers; per-warp register softmax (4-lane shuffles);
// P->A-fragment conversion via warp shuffles; K stored d-pair-interleaved
// so B-fragments load as LDS.64. Two barriers per KV tile.
// ---------------------------------------------------------------------------
#define BQ  128
#define BKV 64

__global__ void __launch_bounds__(256, 2)
attn_tc2(const float* __restrict__ Q, const float* __restrict__ K,
         const float* __restrict__ V, const int* __restrict__ mask,
         float* __restrict__ O) {
    __shared__ unsigned Ks[64][68];   // [kv][d pair-interleaved], pitch 68
    __shared__ unsigned Vs[64][68];   // [kv][d plain]
    __shared__ float    Mb[S_LEN];    // mask bias (0 / -1e9)

    const int bh   = blockIdx.y;
    const int b    = bh / N_HEADS;
    const int h    = bh % N_HEADS;
    const int q0   = blockIdx.x * BQ;
    const int tid  = threadIdx.x;
    const int wid  = tid >> 5;
    const int lane = tid & 31;
    const int g    = lane >> 2;
    const int t4   = lane & 3;

    const float* Qb = Q + (size_t)b * S_LEN * D_MODEL + h * D_K;
    const float* Kb = K + (size_t)b * S_LEN * D_MODEL + h * D_K;
    const float* Vb = V + (size_t)b * S_LEN * D_MODEL + h * D_K;
    const int*   mb = mask + b * S_LEN;

    // mask bias for the whole sequence
    for (int i = tid; i < S_LEN; i += 256)
        Mb[i] = (mb[i] != 0) ? 0.0f : -1e9f;

    // stage Q (128 rows x 64 d) through Ks/Vs, then to registers
#pragma unroll
    for (int i = 0; i < 8; i++) {
        int f = tid + i * 256;
        int r = f >> 4, dq = f & 15;
        float4 v = *(const float4*)(Qb + (size_t)(q0 + r) * D_MODEL + dq * 4);
        unsigned* dst = (r < 64) ? &Ks[r][dq * 4] : &Vs[r - 64][dq * 4];
        *(uint4*)dst = f2tf4(v);
    }
    __syncthreads();

    unsigned qf[8][4];
    {
        int r0 = wid * 16 + g;
        int r1 = r0 + 8;
        const unsigned* row0 = (r0 < 64) ? &Ks[r0][0] : &Vs[r0 - 64][0];
        const unsigned* row1 = (r1 < 64) ? &Ks[r1][0] : &Vs[r1 - 64][0];
#pragma unroll
        for (int kb = 0; kb < 8; kb++) {
            qf[kb][0] = row0[kb * 8 + t4];
            qf[kb][1] = row1[kb * 8 + t4];
            qf[kb][2] = row0[kb * 8 + t4 + 4];
            qf[kb][3] = row1[kb * 8 + t4 + 4];
        }
    }
    __syncthreads();

    float o[8][4];
#pragma unroll
    for (int nt = 0; nt < 8; nt++)
#pragma unroll
        for (int i = 0; i < 4; i++) o[nt][i] = 0.0f;
    float m0 = -1e30f, m1 = -1e30f, l0 = 0.0f, l1 = 0.0f;

    const int  srcA = (lane & 28) | (t4 >> 1);
    const int  srcB = srcA + 2;
    const bool odd  = (t4 & 1) != 0;

    for (int k0 = 0; k0 < S_LEN; k0 += BKV) {
        // load K (pair-interleaved) and V (plain)
#pragma unroll
        for (int i = 0; i < 4; i++) {
            int f = tid + i * 256;
            int r = f >> 4, dq = f & 15;
            float4 kv = *(const float4*)(Kb + (size_t)(k0 + r) * D_MODEL + dq * 4);
            int base = (dq >> 1) * 8 + (dq & 1);
            Ks[r][base + 0] = f2tf(kv.x);
            Ks[r][base + 2] = f2tf(kv.y);
            Ks[r][base + 4] = f2tf(kv.z);
            Ks[r][base + 6] = f2tf(kv.w);
            float4 vv = *(const float4*)(Vb + (size_t)(k0 + r) * D_MODEL + dq * 4);
            *(uint4*)&Vs[r][dq * 4] = f2tf4(vv);
        }
        __syncthreads();

        // S = Q @ K^T  (16 q-rows x 64 kv per warp)
        float s[8][4];
#pragma unroll
        for (int nb = 0; nb < 8; nb++) {
            s[nb][0] = 0.0f; s[nb][1] = 0.0f; s[nb][2] = 0.0f; s[nb][3] = 0.0f;
        }
#pragma unroll
        for (int kb = 0; kb < 8; kb++) {
#pragma unroll
            for (int nb = 0; nb < 8; nb++) {
                uint2 kk2 = *(const uint2*)&Ks[nb * 8 + g][kb * 8 + 2 * t4];
                unsigned bfr[2] = {kk2.x, kk2.y};
                mma8(s[nb], qf[kb], bfr);
            }
        }

        // mask + scale + row max
        float mx0 = -1e30f, mx1 = -1e30f;
#pragma unroll
        for (int nb = 0; nb < 8; nb++) {
            float2 mb2 = *(const float2*)&Mb[k0 + nb * 8 + 2 * t4];
            s[nb][0] = s[nb][0] * 0.125f + mb2.x;
            s[nb][1] = s[nb][1] * 0.125f + mb2.y;
            s[nb][2] = s[nb][2] * 0.125f + mb2.x;
            s[nb][3] = s[nb][3] * 0.125f + mb2.y;
            mx0 = fmaxf(mx0, fmaxf(s[nb][0], s[nb][1]));
            mx1 = fmaxf(mx1, fmaxf(s[nb][2], s[nb][3]));
        }
        mx0 = fmaxf(mx0, __shfl_xor_sync(0xffffffffu, mx0, 1));
        mx0 = fmaxf(mx0, __shfl_xor_sync(0xffffffffu, mx0, 2));
        mx1 = fmaxf(mx1, __shfl_xor_sync(0xffffffffu, mx1, 1));
        mx1 = fmaxf(mx1, __shfl_xor_sync(0xffffffffu, mx1, 2));

        float mn0 = fmaxf(m0, mx0), mn1 = fmaxf(m1, mx1);
        float a0 = __expf(m0 - mn0), a1 = __expf(m1 - mn1);
        m0 = mn0; m1 = mn1;

        float ps0 = 0.0f, ps1 = 0.0f;
#pragma unroll
        for (int nb = 0; nb < 8; nb++) {
            float p0 = __expf(s[nb][0] - mn0); ps0 += p0;
            float p1 = __expf(s[nb][1] - mn0); ps0 += p1;
            float p2 = __expf(s[nb][2] - mn1); ps1 += p2;
            float p3 = __expf(s[nb][3] - mn1); ps1 += p3;
            s[nb][0] = __uint_as_float(f2tf(p0));
            s[nb][1] = __uint_as_float(f2tf(p1));
            s[nb][2] = __uint_as_float(f2tf(p2));
            s[nb][3] = __uint_as_float(f2tf(p3));
        }
        ps0 += __shfl_xor_sync(0xffffffffu, ps0, 1);
        ps0 += __shfl_xor_sync(0xffffffffu, ps0, 2);
        ps1 += __shfl_xor_sync(0xffffffffu, ps1, 1);
        ps1 += __shfl_xor_sync(0xffffffffu, ps1, 2);
        l0 = l0 * a0 + ps0;
        l1 = l1 * a1 + ps1;

        // rescale O
#pragma unroll
        for (int nt = 0; nt < 8; nt++) {
            o[nt][0] *= a0; o[nt][1] *= a0;
            o[nt][2] *= a1; o[nt][3] *= a1;
        }

        // O += P @ V   (P fragments via warp shuffles from score fragments)
#pragma unroll
        for (int kb2 = 0; kb2 < 8; kb2++) {
            unsigned c0 = __float_as_uint(s[kb2][0]);
            unsigned c1 = __float_as_uint(s[kb2][1]);
            unsigned c2 = __float_as_uint(s[kb2][2]);
            unsigned c3 = __float_as_uint(s[kb2][3]);
            unsigned e0 = __shfl_sync(0xffffffffu, c0, srcA);
            unsigned e1 = __shfl_sync(0xffffffffu, c1, srcA);
            unsigned e2 = __shfl_sync(0xffffffffu, c2, srcA);
            unsigned e3 = __shfl_sync(0xffffffffu, c3, srcA);
            unsigned f0 = __shfl_sync(0xffffffffu, c0, srcB);
            unsigned f1 = __shfl_sync(0xffffffffu, c1, srcB);
            unsigned f2 = __shfl_sync(0xffffffffu, c2, srcB);
            unsigned f3 = __shfl_sync(0xffffffffu, c3, srcB);
            unsigned af[4];
            af[0] = odd ? e1 : e0;   // row g,   kv col t4
            af[1] = odd ? e3 : e2;   // row g+8, kv col t4
            af[2] = odd ? f1 : f0;   // row g,   kv col t4+4
            af[3] = odd ? f3 : f2;   // row g+8, kv col t4+4
#pragma unroll
            for (int nt = 0; nt < 8; nt++) {
                unsigned bfr[2] = { Vs[kb2 * 8 + t4][nt * 8 + g],
                                    Vs[kb2 * 8 + t4 + 4][nt * 8 + g] };
                mma8(o[nt], af, bfr);
            }
        }
        __syncthreads();
    }

    // finalize
    float il0 = 1.0f / l0, il1 = 1.0f / l1;
    int r0 = q0 + wid * 16 + g;
    size_t g0 = (size_t)(b * S_LEN + r0) * D_MODEL + h * D_K;
    size_t g1 = (size_t)(b * S_LEN + r0 + 8) * D_MODEL + h * D_K;
#pragma unroll
    for (int nt = 0; nt < 8; nt++) {
        float2 o0 = {o[nt][0] * il0, o[nt][1] * il0};
        float2 o1 = {o[nt][2] * il1, o[nt][3] * il1};
        *(float2*)(O + g0 + nt * 8 + 2 * t4) = o0;
        *(float2*)(O + g1 + nt * 8 + 2 * t4) = o1;
    }
}

// ---------------------------------------------------------------------------
// LayerNorm: one block per row of 768, 256 threads.
// ---------------------------------------------------------------------------
__global__ void layernorm_kernel(const float* __restrict__ in,
                                 const float* __restrict__ gamma,
                                 const float* __restrict__ beta,
                                 float* __restrict__ out) {
    const int row = blockIdx.x;
    const int tid = threadIdx.x;
    const float* x = in + (size_t)row * D_MODEL;
    float* y = out + (size_t)row * D_MODEL;

    float v[3];
    float s = 0.0f, sq = 0.0f;
#pragma unroll
    for (int r = 0; r < 3; r++) {
        v[r] = x[tid + r * 256];
        s  += v[r];
        sq += v[r] * v[r];
    }
#pragma unroll
    for (int off = 16; off > 0; off >>= 1) {
        s  += __shfl_xor_sync(0xffffffffu, s,  off);
        sq += __shfl_xor_sync(0xffffffffu, sq, off);
    }
    __shared__ float ss[8], ssq[8];
    int wid = tid >> 5, lane = tid & 31;
    if (lane == 0) { ss[wid] = s; ssq[wid] = sq; }
    __syncthreads();
    s = 0.0f; sq = 0.0f;
#pragma unroll
    for (int w = 0; w < 8; w++) { s += ss[w]; sq += ssq[w]; }

    const float inv_n = 1.0f / (float)D_MODEL;
    float mean = s * inv_n;
    float var  = sq * inv_n - mean * mean;
    float rstd = rsqrtf(var + 1e-5f);
#pragma unroll
    for (int r = 0; r < 3; r++) {
        int c = tid + r * 256;
        y[c] = (v[r] - mean) * rstd * gamma[c] + beta[c];
    }
}

// ---------------------------------------------------------------------------
// Launch
// ---------------------------------------------------------------------------
extern "C" void kernel_launch(void* const* d_in, const int* in_sizes, int n_in,
                              void* d_out, int out_size) {
    const float* x    = (const float*)d_in[0];
    const int*   mask = (const int*)  d_in[1];
    const float* wq = (const float*)d_in[2];
    const float* bq = (const float*)d_in[3];
    const float* wk = (const float*)d_in[4];
    const float* bk = (const float*)d_in[5];
    const float* wv = (const float*)d_in[6];
    const float* bv = (const float*)d_in[7];
    const float* wo = (const float*)d_in[8];
    const float* bo = (const float*)d_in[9];
    const float* w1 = (const float*)d_in[10];
    const float* b1 = (const float*)d_in[11];
    const float* w2 = (const float*)d_in[12];
    const float* b2 = (const float*)d_in[13];
    const float* g1 = (const float*)d_in[14];
    const float* be1= (const float*)d_in[15];
    const float* g2 = (const float*)d_in[16];
    const float* be2= (const float*)d_in[17];
    float* out = (float*)d_out;

    void* sptr = nullptr;
    cudaGetSymbolAddress(&sptr, g_scratch);
    float* S = (float*)sptr;
    float* q_b = S + OFF_Q;
    float* k_b = S + OFF_K;
    float* v_b = S + OFF_V;
    float* ctx = S + OFF_CTX;
    float* h1  = S + OFF_H1;
    float* x1  = S + OFF_X1;
    float* h2  = S + OFF_H2;
    float* ff  = S + OFF_FF;

    dim3 blk(256);
    dim3 grid_qkv(18, M_ROWS / 128);             // (18, 32) = 576 blocks
    dim3 grid_dm(D_MODEL / 128, M_ROWS / 128);   // (6, 32)
    dim3 grid_ff(D_FF / 128,   M_ROWS / 128);    // (24, 32)

    gemm_qkv<<<grid_qkv, blk>>>(x, wq, wk, wv, bq, bk, bv, q_b, k_b, v_b,
                                M_ROWS, D_MODEL);

    dim3 agrid(S_LEN / BQ, B_SZ * N_HEADS);      // (16, 24)
    attn_tc2<<<agrid, blk>>>(q_b, k_b, v_b, mask, ctx);

    gemm_tc<2><<<grid_dm, blk>>>(ctx, wo, bo, x, h1, M_ROWS, D_MODEL, D_MODEL);
    layernorm_kernel<<<M_ROWS, blk>>>(h1, g1, be1, x1);

    gemm_tc<1><<<grid_ff, blk>>>(x1, w1, b1, nullptr, ff, M_ROWS, D_FF, D_MODEL);
    gemm_tc<2><<<grid_dm, blk>>>(ff, w2, b2, x1, h2, M_ROWS, D_MODEL, D_FF);
    layernorm_kernel<<<M_ROWS, blk>>>(h2, g2, be2, out);
}

// round 7
// speedup vs baseline: 3.5834x; 1.1067x over previous
#include <cuda_runtime.h>
#include <math.h>

// ---------------------------------------------------------------------------
// B=2, S=2048, D=768, H=12, dk=64, FF=3072
// ---------------------------------------------------------------------------
#define B_SZ     2
#define S_LEN    2048
#define D_MODEL  768
#define N_HEADS  12
#define D_K      64
#define D_FF     3072
#define M_ROWS   (B_SZ * S_LEN)           // 4096

#define SZ_DM   (M_ROWS * D_MODEL)
#define SZ_FF   (M_ROWS * D_FF)
__device__ float g_scratch[7 * SZ_DM + SZ_FF];

#define OFF_Q    (0 * SZ_DM)
#define OFF_K    (1 * SZ_DM)
#define OFF_V    (2 * SZ_DM)
#define OFF_CTX  (3 * SZ_DM)
#define OFF_H1   (4 * SZ_DM)
#define OFF_X1   (5 * SZ_DM)
#define OFF_H2   (6 * SZ_DM)
#define OFF_FF   (7 * SZ_DM)

// ---------------------------------------------------------------------------
// helpers: raw fp32 bits fed to mma.tf32 (HW truncates to tf32 — no cvt)
// ---------------------------------------------------------------------------
__device__ __forceinline__ unsigned smem_u32(const void* p) {
    return (unsigned)__cvta_generic_to_shared(p);
}
#define CP16(dst_u32, src_ptr) \
    asm volatile("cp.async.cg.shared.global [%0], [%1], 16;\n" :: "r"(dst_u32), "l"(src_ptr))
#define CP_COMMIT() asm volatile("cp.async.commit_group;\n")
#define CP_WAIT0()  asm volatile("cp.async.wait_group 0;\n")

__device__ __forceinline__ void mma8(float c[4], const unsigned a[4], const unsigned b[2]) {
    asm volatile(
        "mma.sync.aligned.m16n8k8.row.col.f32.tf32.tf32.f32 "
        "{%0,%1,%2,%3}, {%4,%5,%6,%7}, {%8,%9}, {%0,%1,%2,%3};\n"
        : "+f"(c[0]), "+f"(c[1]), "+f"(c[2]), "+f"(c[3])
        : "r"(a[0]), "r"(a[1]), "r"(a[2]), "r"(a[3]), "r"(b[0]), "r"(b[1]));
}

__device__ __forceinline__ float gelu_exact(float x) {
    return 0.5f * x * (1.0f + erff(x * 0.70710678118654752440f));
}

// ---------------------------------------------------------------------------
// GEMM: C[M,N] = A[M,K] @ W[K,N] + bias (+gelu / +residual)
// Block tile 128x128, BK=16, 256 threads (8 warps, 4m x 2n), warp tile 32x64.
// cp.async double-buffered smem (copy overlapped with MMA), no conversions.
//   A smem: [m][k] pitch 20  -> A-frag LDS.32 conflict-free ((20g+t4)%32 distinct)
//   B smem: [k][n] pitch 136 -> B-frag LDS.32 conflict-free ((8t4+g)%32 distinct)
// ---------------------------------------------------------------------------
template <int MODE>   // 0: bias, 1: bias+gelu, 2: bias+residual
__device__ __forceinline__ void gemm_body(
        const float* __restrict__ A, const float* __restrict__ W,
        const float* __restrict__ bias, const float* __restrict__ Res,
        float* __restrict__ C, int M, int N, int K, int bxi, int byi) {
    __shared__ __align__(16) float As[2][128][20];
    __shared__ __align__(16) float Bs[2][16][136];

    const int tid  = threadIdx.x;
    const int wid  = tid >> 5;
    const int lane = tid & 31;
    const int g    = lane >> 2;
    const int t4   = lane & 3;
    const int wm   = wid & 3;
    const int wn   = wid >> 2;
    const int bm   = byi * 128;
    const int bn   = bxi * 128;

    // copy coords
    const int am  = tid >> 2;        // A rows am, am+64 ; 16B chunk akq
    const int akq = tid & 3;
    const int bkr = tid >> 5;        // B rows bkr, bkr+8 ; 16B chunk bnq
    const int bnq = tid & 31;

    const float* Ar0 = A + (size_t)(bm + am) * K + akq * 4;
    const float* Ar1 = A + (size_t)(bm + am + 64) * K + akq * 4;
    const float* Wr0 = W + (size_t)bkr * N + bn + bnq * 4;
    const float* Wr1 = W + (size_t)(bkr + 8) * N + bn + bnq * 4;

    float c[2][8][4];
#pragma unroll
    for (int mt = 0; mt < 2; mt++)
#pragma unroll
        for (int nt = 0; nt < 8; nt++)
#pragma unroll
            for (int i = 0; i < 4; i++) c[mt][nt][i] = 0.0f;

    // prologue: tile 0
    {
        CP16(smem_u32(&As[0][am][akq * 4]),      Ar0);
        CP16(smem_u32(&As[0][am + 64][akq * 4]), Ar1);
        CP16(smem_u32(&Bs[0][bkr][bnq * 4]),     Wr0);
        CP16(smem_u32(&Bs[0][bkr + 8][bnq * 4]), Wr1);
        CP_COMMIT();
        CP_WAIT0();
    }
    __syncthreads();

    int buf = 0;
    for (int k0 = 0; k0 < K; k0 += 16) {
        const bool has_next = (k0 + 16) < K;
        if (has_next) {
            int kn = k0 + 16;
            int nxt = buf ^ 1;
            CP16(smem_u32(&As[nxt][am][akq * 4]),      Ar0 + kn);
            CP16(smem_u32(&As[nxt][am + 64][akq * 4]), Ar1 + kn);
            CP16(smem_u32(&Bs[nxt][bkr][bnq * 4]),     Wr0 + (size_t)kn * N);
            CP16(smem_u32(&Bs[nxt][bkr + 8][bnq * 4]), Wr1 + (size_t)kn * N);
            CP_COMMIT();
        }

#pragma unroll
        for (int kb = 0; kb < 2; kb++) {
            const int kk = kb * 8;
            unsigned a[2][4], b[8][2];
#pragma unroll
            for (int mt = 0; mt < 2; mt++) {
                const float* r0 = &As[buf][wm * 32 + mt * 16 + g][kk + t4];
                a[mt][0] = __float_as_uint(r0[0]);
                a[mt][1] = __float_as_uint(r0[8 * 20]);
                a[mt][2] = __float_as_uint(r0[4]);
                a[mt][3] = __float_as_uint(r0[8 * 20 + 4]);
            }
#pragma unroll
            for (int nt = 0; nt < 8; nt++) {
                int cb = wn * 64 + nt * 8;
                b[nt][0] = __float_as_uint(Bs[buf][kk + t4][cb + g]);
                b[nt][1] = __float_as_uint(Bs[buf][kk + t4 + 4][cb + g]);
            }
#pragma unroll
            for (int mt = 0; mt < 2; mt++)
#pragma unroll
                for (int nt = 0; nt < 8; nt++)
                    mma8(c[mt][nt], a[mt], b[nt]);
        }

        if (has_next) CP_WAIT0();
        __syncthreads();
        buf ^= 1;
    }

    // epilogue
#pragma unroll
    for (int mt = 0; mt < 2; mt++) {
        int r0 = bm + wm * 32 + mt * 16 + g;
        int r1 = r0 + 8;
#pragma unroll
        for (int nt = 0; nt < 8; nt++) {
            int col = bn + wn * 64 + nt * 8 + t4 * 2;
            float bb0 = bias[col], bb1 = bias[col + 1];
            float v00 = c[mt][nt][0] + bb0;
            float v01 = c[mt][nt][1] + bb1;
            float v10 = c[mt][nt][2] + bb0;
            float v11 = c[mt][nt][3] + bb1;
            if (MODE == 1) {
                v00 = gelu_exact(v00); v01 = gelu_exact(v01);
                v10 = gelu_exact(v10); v11 = gelu_exact(v11);
            }
            if (MODE == 2) {
                float2 r0v = *(const float2*)(Res + (size_t)r0 * N + col);
                float2 r1v = *(const float2*)(Res + (size_t)r1 * N + col);
                v00 += r0v.x; v01 += r0v.y; v10 += r1v.x; v11 += r1v.y;
            }
            float2 o0 = {v00, v01}, o1 = {v10, v11};
            *(float2*)(C + (size_t)r0 * N + col) = o0;
            *(float2*)(C + (size_t)r1 * N + col) = o1;
        }
    }
}

template <int MODE>
__global__ void __launch_bounds__(256)
gemm_tc(const float* __restrict__ A, const float* __restrict__ W,
        const float* __restrict__ bias, const float* __restrict__ Res,
        float* __restrict__ C, int M, int N, int K) {
    gemm_body<MODE>(A, W, bias, Res, C, M, N, K, blockIdx.x, blockIdx.y);
}

// Fused QKV: grid.x = 18 (6 col-blocks per projection), selects W/bias/output.
__global__ void __launch_bounds__(256)
gemm_qkv(const float* __restrict__ A,
         const float* __restrict__ Wq, const float* __restrict__ Wk, const float* __restrict__ Wv,
         const float* __restrict__ bq, const float* __restrict__ bk, const float* __restrict__ bv,
         float* __restrict__ Oq, float* __restrict__ Ok, float* __restrict__ Ov,
         int M, int K) {
    int sel = blockIdx.x / 6;
    int bx  = blockIdx.x - sel * 6;
    const float* W    = (sel == 0) ? Wq : (sel == 1) ? Wk : Wv;
    const float* bias = (sel == 0) ? bq : (sel == 1) ? bk : bv;
    float*       C    = (sel == 0) ? Oq : (sel == 1) ? Ok : Ov;
    gemm_body<0>(A, W, bias, nullptr, C, M, D_MODEL, K, bx, blockIdx.y);
}

// ---------------------------------------------------------------------------
// Flash attention: BQ=128 (16 q-rows per warp, 8 warps), BKV=64.
// Q fragments in registers; register softmax (4-lane shuffles); P->A-fragment
// via warp shuffles; K d-pair-interleaved (LDS.64 B-frags); V via cp.async.
// No tf32 conversions anywhere (raw fp32 bits truncate in HW).
// occupancy 3 -> whole 384-block grid resident in one wave.
// ---------------------------------------------------------------------------
#define BQ  128
#define BKV 64

__global__ void __launch_bounds__(256, 3)
attn_tc2(const float* __restrict__ Q, const float* __restrict__ K,
         const float* __restrict__ V, const int* __restrict__ mask,
         float* __restrict__ O) {
    __shared__ __align__(16) unsigned Ks[64][68];   // [kv][d pair-interleaved]
    __shared__ __align__(16) float    Vs[64][68];   // [kv][d plain]
    __shared__ float Mb[S_LEN];                     // mask bias (0 / -1e9)

    const int bh   = blockIdx.y;
    const int b    = bh / N_HEADS;
    const int h    = bh % N_HEADS;
    const int q0   = blockIdx.x * BQ;
    const int tid  = threadIdx.x;
    const int wid  = tid >> 5;
    const int lane = tid & 31;
    const int g    = lane >> 2;
    const int t4   = lane & 3;

    const float* Qb = Q + (size_t)b * S_LEN * D_MODEL + h * D_K;
    const float* Kb = K + (size_t)b * S_LEN * D_MODEL + h * D_K;
    const float* Vb = V + (size_t)b * S_LEN * D_MODEL + h * D_K;
    const int*   mb = mask + b * S_LEN;

    // mask bias for the whole sequence
    for (int i = tid; i < S_LEN; i += 256)
        Mb[i] = (mb[i] != 0) ? 0.0f : -1e9f;

    // stage Q (128 rows x 64 d) through Ks/Vs, then to registers (raw bits)
#pragma unroll
    for (int i = 0; i < 8; i++) {
        int f = tid + i * 256;
        int r = f >> 4, dq = f & 15;
        float4 v = *(const float4*)(Qb + (size_t)(q0 + r) * D_MODEL + dq * 4);
        if (r < 64) {
            uint4 u = {__float_as_uint(v.x), __float_as_uint(v.y),
                       __float_as_uint(v.z), __float_as_uint(v.w)};
            *(uint4*)&Ks[r][dq * 4] = u;
        } else {
            *(float4*)&Vs[r - 64][dq * 4] = v;
        }
    }
    __syncthreads();

    unsigned qf[8][4];
    {
        int r0 = wid * 16 + g;
        int r1 = r0 + 8;
        const unsigned* row0 = (r0 < 64) ? &Ks[r0][0] : (const unsigned*)&Vs[r0 - 64][0];
        const unsigned* row1 = (r1 < 64) ? &Ks[r1][0] : (const unsigned*)&Vs[r1 - 64][0];
#pragma unroll
        for (int kb = 0; kb < 8; kb++) {
            qf[kb][0] = row0[kb * 8 + t4];
            qf[kb][1] = row1[kb * 8 + t4];
            qf[kb][2] = row0[kb * 8 + t4 + 4];
            qf[kb][3] = row1[kb * 8 + t4 + 4];
        }
    }
    __syncthreads();

    float o[8][4];
#pragma unroll
    for (int nt = 0; nt < 8; nt++)
#pragma unroll
        for (int i = 0; i < 4; i++) o[nt][i] = 0.0f;
    float m0 = -1e30f, m1 = -1e30f, l0 = 0.0f, l1 = 0.0f;

    const int  srcA = (lane & 28) | (t4 >> 1);
    const int  srcB = srcA + 2;
    const bool odd  = (t4 & 1) != 0;

    for (int k0 = 0; k0 < S_LEN; k0 += BKV) {
        // V tile via cp.async (overlaps with the K register path below)
#pragma unroll
        for (int i = 0; i < 4; i++) {
            int f = tid + i * 256;
            int r = f >> 4, dq = f & 15;
            CP16(smem_u32(&Vs[r][dq * 4]), Vb + (size_t)(k0 + r) * D_MODEL + dq * 4);
        }
        CP_COMMIT();
        // K tile: pair-interleaved store (raw bits, no cvt)
#pragma unroll
        for (int i = 0; i < 4; i++) {
            int f = tid + i * 256;
            int r = f >> 4, dq = f & 15;
            float4 kv = *(const float4*)(Kb + (size_t)(k0 + r) * D_MODEL + dq * 4);
            int base = (dq >> 1) * 8 + (dq & 1);
            Ks[r][base + 0] = __float_as_uint(kv.x);
            Ks[r][base + 2] = __float_as_uint(kv.y);
            Ks[r][base + 4] = __float_as_uint(kv.z);
            Ks[r][base + 6] = __float_as_uint(kv.w);
        }
        CP_WAIT0();
        __syncthreads();

        // S = Q @ K^T  (16 q-rows x 64 kv per warp)
        float s[8][4];
#pragma unroll
        for (int nb = 0; nb < 8; nb++) {
            s[nb][0] = 0.0f; s[nb][1] = 0.0f; s[nb][2] = 0.0f; s[nb][3] = 0.0f;
        }
#pragma unroll
        for (int kb = 0; kb < 8; kb++) {
#pragma unroll
            for (int nb = 0; nb < 8; nb++) {
                uint2 kk2 = *(const uint2*)&Ks[nb * 8 + g][kb * 8 + 2 * t4];
                unsigned bfr[2] = {kk2.x, kk2.y};
                mma8(s[nb], qf[kb], bfr);
            }
        }

        // mask + scale + row max
        float mx0 = -1e30f, mx1 = -1e30f;
#pragma unroll
        for (int nb = 0; nb < 8; nb++) {
            float2 mb2 = *(const float2*)&Mb[k0 + nb * 8 + 2 * t4];
            s[nb][0] = s[nb][0] * 0.125f + mb2.x;
            s[nb][1] = s[nb][1] * 0.125f + mb2.y;
            s[nb][2] = s[nb][2] * 0.125f + mb2.x;
            s[nb][3] = s[nb][3] * 0.125f + mb2.y;
            mx0 = fmaxf(mx0, fmaxf(s[nb][0], s[nb][1]));
            mx1 = fmaxf(mx1, fmaxf(s[nb][2], s[nb][3]));
        }
        mx0 = fmaxf(mx0, __shfl_xor_sync(0xffffffffu, mx0, 1));
        mx0 = fmaxf(mx0, __shfl_xor_sync(0xffffffffu, mx0, 2));
        mx1 = fmaxf(mx1, __shfl_xor_sync(0xffffffffu, mx1, 1));
        mx1 = fmaxf(mx1, __shfl_xor_sync(0xffffffffu, mx1, 2));

        float mn0 = fmaxf(m0, mx0), mn1 = fmaxf(m1, mx1);
        float a0 = __expf(m0 - mn0), a1 = __expf(m1 - mn1);
        m0 = mn0; m1 = mn1;

        float ps0 = 0.0f, ps1 = 0.0f;
#pragma unroll
        for (int nb = 0; nb < 8; nb++) {
            float p0 = __expf(s[nb][0] - mn0); ps0 += p0;
            float p1 = __expf(s[nb][1] - mn0); ps0 += p1;
            float p2 = __expf(s[nb][2] - mn1); ps1 += p2;
            float p3 = __expf(s[nb][3] - mn1); ps1 += p3;
            s[nb][0] = p0; s[nb][1] = p1; s[nb][2] = p2; s[nb][3] = p3;
        }
        ps0 += __shfl_xor_sync(0xffffffffu, ps0, 1);
        ps0 += __shfl_xor_sync(0xffffffffu, ps0, 2);
        ps1 += __shfl_xor_sync(0xffffffffu, ps1, 1);
        ps1 += __shfl_xor_sync(0xffffffffu, ps1, 2);
        l0 = l0 * a0 + ps0;
        l1 = l1 * a1 + ps1;

        // rescale O
#pragma unroll
        for (int nt = 0; nt < 8; nt++) {
            o[nt][0] *= a0; o[nt][1] *= a0;
            o[nt][2] *= a1; o[nt][3] *= a1;
        }

        // O += P @ V   (P fragments via warp shuffles from score fragments)
#pragma unroll
        for (int kb2 = 0; kb2 < 8; kb2++) {
            unsigned c0 = __float_as_uint(s[kb2][0]);
            unsigned c1 = __float_as_uint(s[kb2][1]);
            unsigned c2 = __float_as_uint(s[kb2][2]);
            unsigned c3 = __float_as_uint(s[kb2][3]);
            unsigned e0 = __shfl_sync(0xffffffffu, c0, srcA);
            unsigned e1 = __shfl_sync(0xffffffffu, c1, srcA);
            unsigned e2 = __shfl_sync(0xffffffffu, c2, srcA);
            unsigned e3 = __shfl_sync(0xffffffffu, c3, srcA);
            unsigned f0 = __shfl_sync(0xffffffffu, c0, srcB);
            unsigned f1 = __shfl_sync(0xffffffffu, c1, srcB);
            unsigned f2 = __shfl_sync(0xffffffffu, c2, srcB);
            unsigned f3 = __shfl_sync(0xffffffffu, c3, srcB);
            unsigned af[4];
            af[0] = odd ? e1 : e0;   // row g,   kv col t4
            af[1] = odd ? e3 : e2;   // row g+8, kv col t4
            af[2] = odd ? f1 : f0;   // row g,   kv col t4+4
            af[3] = odd ? f3 : f2;   // row g+8, kv col t4+4
#pragma unroll
            for (int nt = 0; nt < 8; nt++) {
                unsigned bfr[2] = { __float_as_uint(Vs[kb2 * 8 + t4][nt * 8 + g]),
                                    __float_as_uint(Vs[kb2 * 8 + t4 + 4][nt * 8 + g]) };
                mma8(o[nt], af, bfr);
            }
        }
        __syncthreads();
    }

    // finalize
    float il0 = 1.0f / l0, il1 = 1.0f / l1;
    int r0 = q0 + wid * 16 + g;
    size_t g0 = (size_t)(b * S_LEN + r0) * D_MODEL + h * D_K;
    size_t g1 = (size_t)(b * S_LEN + r0 + 8) * D_MODEL + h * D_K;
#pragma unroll
    for (int nt = 0; nt < 8; nt++) {
        float2 o0 = {o[nt][0] * il0, o[nt][1] * il0};
        float2 o1 = {o[nt][2] * il1, o[nt][3] * il1};
        *(float2*)(O + g0 + nt * 8 + 2 * t4) = o0;
        *(float2*)(O + g1 + nt * 8 + 2 * t4) = o1;
    }
}

// ---------------------------------------------------------------------------
// LayerNorm: one block per row of 768, 256 threads.
// ---------------------------------------------------------------------------
__global__ void layernorm_kernel(const float* __restrict__ in,
                                 const float* __restrict__ gamma,
                                 const float* __restrict__ beta,
                                 float* __restrict__ out) {
    const int row = blockIdx.x;
    const int tid = threadIdx.x;
    const float* x = in + (size_t)row * D_MODEL;
    float* y = out + (size_t)row * D_MODEL;

    float v[3];
    float s = 0.0f, sq = 0.0f;
#pragma unroll
    for (int r = 0; r < 3; r++) {
        v[r] = x[tid + r * 256];
        s  += v[r];
        sq += v[r] * v[r];
    }
#pragma unroll
    for (int off = 16; off > 0; off >>= 1) {
        s  += __shfl_xor_sync(0xffffffffu, s,  off);
        sq += __shfl_xor_sync(0xffffffffu, sq, off);
    }
    __shared__ float ss[8], ssq[8];
    int wid = tid >> 5, lane = tid & 31;
    if (lane == 0) { ss[wid] = s; ssq[wid] = sq; }
    __syncthreads();
    s = 0.0f; sq = 0.0f;
#pragma unroll
    for (int w = 0; w < 8; w++) { s += ss[w]; sq += ssq[w]; }

    const float inv_n = 1.0f / (float)D_MODEL;
    float mean = s * inv_n;
    float var  = sq * inv_n - mean * mean;
    float rstd = rsqrtf(var + 1e-5f);
#pragma unroll
    for (int r = 0; r < 3; r++) {
        int c = tid + r * 256;
        y[c] = (v[r] - mean) * rstd * gamma[c] + beta[c];
    }
}

// ---------------------------------------------------------------------------
// Launch
// ---------------------------------------------------------------------------
extern "C" void kernel_launch(void* const* d_in, const int* in_sizes, int n_in,
                              void* d_out, int out_size) {
    const float* x    = (const float*)d_in[0];
    const int*   mask = (const int*)  d_in[1];
    const float* wq = (const float*)d_in[2];
    const float* bq = (const float*)d_in[3];
    const float* wk = (const float*)d_in[4];
    const float* bk = (const float*)d_in[5];
    const float* wv = (const float*)d_in[6];
    const float* bv = (const float*)d_in[7];
    const float* wo = (const float*)d_in[8];
    const float* bo = (const float*)d_in[9];
    const float* w1 = (const float*)d_in[10];
    const float* b1 = (const float*)d_in[11];
    const float* w2 = (const float*)d_in[12];
    const float* b2 = (const float*)d_in[13];
    const float* g1 = (const float*)d_in[14];
    const float* be1= (const float*)d_in[15];
    const float* g2 = (const float*)d_in[16];
    const float* be2= (const float*)d_in[17];
    float* out = (float*)d_out;

    void* sptr = nullptr;
    cudaGetSymbolAddress(&sptr, g_scratch);
    float* S = (float*)sptr;
    float* q_b = S + OFF_Q;
    float* k_b = S + OFF_K;
    float* v_b = S + OFF_V;
    float* ctx = S + OFF_CTX;
    float* h1  = S + OFF_H1;
    float* x1  = S + OFF_X1;
    float* h2  = S + OFF_H2;
    float* ff  = S + OFF_FF;

    dim3 blk(256);
    dim3 grid_qkv(18, M_ROWS / 128);             // (18, 32) = 576 blocks
    dim3 grid_dm(D_MODEL / 128, M_ROWS / 128);   // (6, 32)
    dim3 grid_ff(D_FF / 128,   M_ROWS / 128);    // (24, 32)

    gemm_qkv<<<grid_qkv, blk>>>(x, wq, wk, wv, bq, bk, bv, q_b, k_b, v_b,
                                M_ROWS, D_MODEL);

    dim3 agrid(S_LEN / BQ, B_SZ * N_HEADS);      // (16, 24)
    attn_tc2<<<agrid, blk>>>(q_b, k_b, v_b, mask, ctx);

    gemm_tc<2><<<grid_dm, blk>>>(ctx, wo, bo, x, h1, M_ROWS, D_MODEL, D_MODEL);
    layernorm_kernel<<<M_ROWS, blk>>>(h1, g1, be1, x1);

    gemm_tc<1><<<grid_ff, blk>>>(x1, w1, b1, nullptr, ff, M_ROWS, D_FF, D_MODEL);
    gemm_tc<2><<<grid_dm, blk>>>(ff, w2, b2, x1, h2, M_ROWS, D_MODEL, D_FF);
    layernorm_kernel<<<M_ROWS, blk>>>(h2, g2, be2, out);
}

// round 8
// speedup vs baseline: 3.8431x; 1.0725x over previous
#include <cuda_runtime.h>
#include <math.h>

// ---------------------------------------------------------------------------
// B=2, S=2048, D=768, H=12, dk=64, FF=3072
// ---------------------------------------------------------------------------
#define B_SZ     2
#define S_LEN    2048
#define D_MODEL  768
#define N_HEADS  12
#define D_K      64
#define D_FF     3072
#define M_ROWS   (B_SZ * S_LEN)           // 4096

#define SZ_DM   (M_ROWS * D_MODEL)
#define SZ_FF   (M_ROWS * D_FF)
__device__ float g_scratch[7 * SZ_DM + SZ_FF];

#define OFF_Q    (0 * SZ_DM)
#define OFF_K    (1 * SZ_DM)
#define OFF_V    (2 * SZ_DM)
#define OFF_CTX  (3 * SZ_DM)
#define OFF_H1   (4 * SZ_DM)
#define OFF_X1   (5 * SZ_DM)
#define OFF_H2   (6 * SZ_DM)
#define OFF_FF   (7 * SZ_DM)

// ---------------------------------------------------------------------------
// helpers: raw fp32 bits fed to mma.tf32 (HW truncates to tf32 — no cvt)
// ---------------------------------------------------------------------------
__device__ __forceinline__ unsigned smem_u32(const void* p) {
    return (unsigned)__cvta_generic_to_shared(p);
}
#define CP16(dst_u32, src_ptr) \
    asm volatile("cp.async.cg.shared.global [%0], [%1], 16;\n" :: "r"(dst_u32), "l"(src_ptr))
#define CP_COMMIT() asm volatile("cp.async.commit_group;\n")
#define CP_WAIT0()  asm volatile("cp.async.wait_group 0;\n")

__device__ __forceinline__ void mma8(float c[4], const unsigned a[4], const unsigned b[2]) {
    asm volatile(
        "mma.sync.aligned.m16n8k8.row.col.f32.tf32.tf32.f32 "
        "{%0,%1,%2,%3}, {%4,%5,%6,%7}, {%8,%9}, {%0,%1,%2,%3};\n"
        : "+f"(c[0]), "+f"(c[1]), "+f"(c[2]), "+f"(c[3])
        : "r"(a[0]), "r"(a[1]), "r"(a[2]), "r"(a[3]), "r"(b[0]), "r"(b[1]));
}

__device__ __forceinline__ float gelu_exact(float x) {
    return 0.5f * x * (1.0f + erff(x * 0.70710678118654752440f));
}

// ---------------------------------------------------------------------------
// GEMM: C[M,N] = A[M,K] @ W[K,N] + bias (+gelu / +residual)
// Block tile 128x128, BK=32, 256 threads (8 warps, 4m x 2n), warp tile 32x64.
// cp.async double-buffered DYNAMIC smem; one barrier per 32-K tile.
//   A smem: [m][k] pitch 36  -> A-frag LDS.32 conflict-free ((4r+t4)%32 distinct)
//   B smem: [k][n] pitch 136 -> B-frag LDS.32 conflict-free ((8t4+g)%32 distinct)
// ---------------------------------------------------------------------------
#define GEMM_SMEM_FLOATS (2 * 128 * 36 + 2 * 32 * 136)
#define GEMM_SMEM_BYTES  (GEMM_SMEM_FLOATS * 4)

template <int MODE>   // 0: bias, 1: bias+gelu, 2: bias+residual
__device__ __forceinline__ void gemm_body(
        const float* __restrict__ A, const float* __restrict__ W,
        const float* __restrict__ bias, const float* __restrict__ Res,
        float* __restrict__ C, int M, int N, int K, int bxi, int byi) {
    extern __shared__ __align__(16) float smem_dyn[];
    float* As = smem_dyn;                      // [2][128][36]
    float* Bs = smem_dyn + 2 * 128 * 36;       // [2][32][136]
#define AS(s, r, c) As[((s) * 128 + (r)) * 36 + (c)]
#define BS(s, r, c) Bs[((s) * 32 + (r)) * 136 + (c)]

    const int tid  = threadIdx.x;
    const int wid  = tid >> 5;
    const int lane = tid & 31;
    const int g    = lane >> 2;
    const int t4   = lane & 3;
    const int wm   = wid & 3;
    const int wn   = wid >> 2;
    const int bm   = byi * 128;
    const int bn   = bxi * 128;

    float c[2][8][4];
#pragma unroll
    for (int mt = 0; mt < 2; mt++)
#pragma unroll
        for (int nt = 0; nt < 8; nt++)
#pragma unroll
            for (int i = 0; i < 4; i++) c[mt][nt][i] = 0.0f;

    // tile copy: A 128x32 (1024 chunks), B 32x128 (1024 chunks), 4+4 CP16/thread
    const int ar = tid >> 3, aq = tid & 7;     // base A coords (row step 32)
    const int br = tid >> 5, bq = tid & 31;    // base B coords (row step 8)

#define LOAD_TILE(stage, kbase)                                                  \
    do {                                                                         \
        _Pragma("unroll")                                                        \
        for (int i = 0; i < 4; i++) {                                            \
            int r = ar + i * 32;                                                 \
            CP16(smem_u32(&AS(stage, r, aq * 4)),                                \
                 A + (size_t)(bm + r) * K + (kbase) + aq * 4);                   \
        }                                                                        \
        _Pragma("unroll")                                                        \
        for (int i = 0; i < 4; i++) {                                            \
            int r = br + i * 8;                                                  \
            CP16(smem_u32(&BS(stage, r, bq * 4)),                                \
                 W + (size_t)((kbase) + r) * N + bn + bq * 4);                   \
        }                                                                        \
        CP_COMMIT();                                                             \
    } while (0)

    LOAD_TILE(0, 0);
    CP_WAIT0();
    __syncthreads();

    int buf = 0;
    for (int k0 = 0; k0 < K; k0 += 32) {
        const bool has_next = (k0 + 32) < K;
        if (has_next) LOAD_TILE(buf ^ 1, k0 + 32);

#pragma unroll
        for (int kb = 0; kb < 4; kb++) {
            const int kk = kb * 8;
            unsigned a[2][4], b[8][2];
#pragma unroll
            for (int mt = 0; mt < 2; mt++) {
                int r = wm * 32 + mt * 16 + g;
                a[mt][0] = __float_as_uint(AS(buf, r,     kk + t4));
                a[mt][1] = __float_as_uint(AS(buf, r + 8, kk + t4));
                a[mt][2] = __float_as_uint(AS(buf, r,     kk + t4 + 4));
                a[mt][3] = __float_as_uint(AS(buf, r + 8, kk + t4 + 4));
            }
#pragma unroll
            for (int nt = 0; nt < 8; nt++) {
                int cb = wn * 64 + nt * 8;
                b[nt][0] = __float_as_uint(BS(buf, kk + t4,     cb + g));
                b[nt][1] = __float_as_uint(BS(buf, kk + t4 + 4, cb + g));
            }
#pragma unroll
            for (int mt = 0; mt < 2; mt++)
#pragma unroll
                for (int nt = 0; nt < 8; nt++)
                    mma8(c[mt][nt], a[mt], b[nt]);
        }

        if (has_next) CP_WAIT0();
        __syncthreads();
        buf ^= 1;
    }

    // epilogue
#pragma unroll
    for (int mt = 0; mt < 2; mt++) {
        int r0 = bm + wm * 32 + mt * 16 + g;
        int r1 = r0 + 8;
#pragma unroll
        for (int nt = 0; nt < 8; nt++) {
            int col = bn + wn * 64 + nt * 8 + t4 * 2;
            float bb0 = bias[col], bb1 = bias[col + 1];
            float v00 = c[mt][nt][0] + bb0;
            float v01 = c[mt][nt][1] + bb1;
            float v10 = c[mt][nt][2] + bb0;
            float v11 = c[mt][nt][3] + bb1;
            if (MODE == 1) {
                v00 = gelu_exact(v00); v01 = gelu_exact(v01);
                v10 = gelu_exact(v10); v11 = gelu_exact(v11);
            }
            if (MODE == 2) {
                float2 r0v = *(const float2*)(Res + (size_t)r0 * N + col);
                float2 r1v = *(const float2*)(Res + (size_t)r1 * N + col);
                v00 += r0v.x; v01 += r0v.y; v10 += r1v.x; v11 += r1v.y;
            }
            float2 o0 = {v00, v01}, o1 = {v10, v11};
            *(float2*)(C + (size_t)r0 * N + col) = o0;
            *(float2*)(C + (size_t)r1 * N + col) = o1;
        }
    }
#undef AS
#undef BS
}

template <int MODE>
__global__ void __launch_bounds__(256)
gemm_tc(const float* __restrict__ A, const float* __restrict__ W,
        const float* __restrict__ bias, const float* __restrict__ Res,
        float* __restrict__ C, int M, int N, int K) {
    gemm_body<MODE>(A, W, bias, Res, C, M, N, K, blockIdx.x, blockIdx.y);
}

// Fused QKV: grid.x = 18 (6 col-blocks per projection), selects W/bias/output.
__global__ void __launch_bounds__(256)
gemm_qkv(const float* __restrict__ A,
         const float* __restrict__ Wq, const float* __restrict__ Wk, const float* __restrict__ Wv,
         const float* __restrict__ bq, const float* __restrict__ bk, const float* __restrict__ bv,
         float* __restrict__ Oq, float* __restrict__ Ok, float* __restrict__ Ov,
         int M, int K) {
    int sel = blockIdx.x / 6;
    int bx  = blockIdx.x - sel * 6;
    const float* W    = (sel == 0) ? Wq : (sel == 1) ? Wk : Wv;
    const float* bias = (sel == 0) ? bq : (sel == 1) ? bk : bv;
    float*       C    = (sel == 0) ? Oq : (sel == 1) ? Ok : Ov;
    gemm_body<0>(A, W, bias, nullptr, C, M, D_MODEL, K, bx, blockIdx.y);
}

// ---------------------------------------------------------------------------
// Flash attention: BQ=128 (16 q-rows per warp, 8 warps), BKV=64.
// Q fragments in registers; register softmax (4-lane shuffles); P->A-fragment
// via warp shuffles; K d-pair-interleaved (LDS.64 B-frags); V via cp.async.
// ---------------------------------------------------------------------------
#define BQ  128
#define BKV 64

__global__ void __launch_bounds__(256, 3)
attn_tc2(const float* __restrict__ Q, const float* __restrict__ K,
         const float* __restrict__ V, const int* __restrict__ mask,
         float* __restrict__ O) {
    __shared__ __align__(16) unsigned Ks[64][68];   // [kv][d pair-interleaved]
    __shared__ __align__(16) float    Vs[64][68];   // [kv][d plain]
    __shared__ float Mb[S_LEN];                     // mask bias (0 / -1e9)

    const int bh   = blockIdx.y;
    const int b    = bh / N_HEADS;
    const int h    = bh % N_HEADS;
    const int q0   = blockIdx.x * BQ;
    const int tid  = threadIdx.x;
    const int wid  = tid >> 5;
    const int lane = tid & 31;
    const int g    = lane >> 2;
    const int t4   = lane & 3;

    const float* Qb = Q + (size_t)b * S_LEN * D_MODEL + h * D_K;
    const float* Kb = K + (size_t)b * S_LEN * D_MODEL + h * D_K;
    const float* Vb = V + (size_t)b * S_LEN * D_MODEL + h * D_K;
    const int*   mb = mask + b * S_LEN;

    for (int i = tid; i < S_LEN; i += 256)
        Mb[i] = (mb[i] != 0) ? 0.0f : -1e9f;

    // stage Q (128 rows x 64 d) through Ks/Vs, then to registers (raw bits)
#pragma unroll
    for (int i = 0; i < 8; i++) {
        int f = tid + i * 256;
        int r = f >> 4, dq = f & 15;
        float4 v = *(const float4*)(Qb + (size_t)(q0 + r) * D_MODEL + dq * 4);
        if (r < 64) {
            uint4 u = {__float_as_uint(v.x), __float_as_uint(v.y),
                       __float_as_uint(v.z), __float_as_uint(v.w)};
            *(uint4*)&Ks[r][dq * 4] = u;
        } else {
            *(float4*)&Vs[r - 64][dq * 4] = v;
        }
    }
    __syncthreads();

    unsigned qf[8][4];
    {
        int r0 = wid * 16 + g;
        int r1 = r0 + 8;
        const unsigned* row0 = (r0 < 64) ? &Ks[r0][0] : (const unsigned*)&Vs[r0 - 64][0];
        const unsigned* row1 = (r1 < 64) ? &Ks[r1][0] : (const unsigned*)&Vs[r1 - 64][0];
#pragma unroll
        for (int kb = 0; kb < 8; kb++) {
            qf[kb][0] = row0[kb * 8 + t4];
            qf[kb][1] = row1[kb * 8 + t4];
            qf[kb][2] = row0[kb * 8 + t4 + 4];
            qf[kb][3] = row1[kb * 8 + t4 + 4];
        }
    }
    __syncthreads();

    float o[8][4];
#pragma unroll
    for (int nt = 0; nt < 8; nt++)
#pragma unroll
        for (int i = 0; i < 4; i++) o[nt][i] = 0.0f;
    float m0 = -1e30f, m1 = -1e30f, l0 = 0.0f, l1 = 0.0f;

    const int  srcA = (lane & 28) | (t4 >> 1);
    const int  srcB = srcA + 2;
    const bool odd  = (t4 & 1) != 0;

    for (int k0 = 0; k0 < S_LEN; k0 += BKV) {
        // V tile via cp.async (overlaps with the K register path below)
#pragma unroll
        for (int i = 0; i < 4; i++) {
            int f = tid + i * 256;
            int r = f >> 4, dq = f & 15;
            CP16(smem_u32(&Vs[r][dq * 4]), Vb + (size_t)(k0 + r) * D_MODEL + dq * 4);
        }
        CP_COMMIT();
        // K tile: pair-interleaved store (raw bits, no cvt)
#pragma unroll
        for (int i = 0; i < 4; i++) {
            int f = tid + i * 256;
            int r = f >> 4, dq = f & 15;
            float4 kv = *(const float4*)(Kb + (size_t)(k0 + r) * D_MODEL + dq * 4);
            int base = (dq >> 1) * 8 + (dq & 1);
            Ks[r][base + 0] = __float_as_uint(kv.x);
            Ks[r][base + 2] = __float_as_uint(kv.y);
            Ks[r][base + 4] = __float_as_uint(kv.z);
            Ks[r][base + 6] = __float_as_uint(kv.w);
        }
        CP_WAIT0();
        __syncthreads();

        // S = Q @ K^T  (16 q-rows x 64 kv per warp)
        float s[8][4];
#pragma unroll
        for (int nb = 0; nb < 8; nb++) {
            s[nb][0] = 0.0f; s[nb][1] = 0.0f; s[nb][2] = 0.0f; s[nb][3] = 0.0f;
        }
#pragma unroll
        for (int kb = 0; kb < 8; kb++) {
#pragma unroll
            for (int nb = 0; nb < 8; nb++) {
                uint2 kk2 = *(const uint2*)&Ks[nb * 8 + g][kb * 8 + 2 * t4];
                unsigned bfr[2] = {kk2.x, kk2.y};
                mma8(s[nb], qf[kb], bfr);
            }
        }

        // mask + scale + row max
        float mx0 = -1e30f, mx1 = -1e30f;
#pragma unroll
        for (int nb = 0; nb < 8; nb++) {
            float2 mb2 = *(const float2*)&Mb[k0 + nb * 8 + 2 * t4];
            s[nb][0] = s[nb][0] * 0.125f + mb2.x;
            s[nb][1] = s[nb][1] * 0.125f + mb2.y;
            s[nb][2] = s[nb][2] * 0.125f + mb2.x;
            s[nb][3] = s[nb][3] * 0.125f + mb2.y;
            mx0 = fmaxf(mx0, fmaxf(s[nb][0], s[nb][1]));
            mx1 = fmaxf(mx1, fmaxf(s[nb][2], s[nb][3]));
        }
        mx0 = fmaxf(mx0, __shfl_xor_sync(0xffffffffu, mx0, 1));
        mx0 = fmaxf(mx0, __shfl_xor_sync(0xffffffffu, mx0, 2));
        mx1 = fmaxf(mx1, __shfl_xor_sync(0xffffffffu, mx1, 1));
        mx1 = fmaxf(mx1, __shfl_xor_sync(0xffffffffu, mx1, 2));

        float mn0 = fmaxf(m0, mx0), mn1 = fmaxf(m1, mx1);
        float a0 = __expf(m0 - mn0), a1 = __expf(m1 - mn1);
        m0 = mn0; m1 = mn1;

        float ps0 = 0.0f, ps1 = 0.0f;
#pragma unroll
        for (int nb = 0; nb < 8; nb++) {
            float p0 = __expf(s[nb][0] - mn0); ps0 += p0;
            float p1 = __expf(s[nb][1] - mn0); ps0 += p1;
            float p2 = __expf(s[nb][2] - mn1); ps1 += p2;
            float p3 = __expf(s[nb][3] - mn1); ps1 += p3;
            s[nb][0] = p0; s[nb][1] = p1; s[nb][2] = p2; s[nb][3] = p3;
        }
        ps0 += __shfl_xor_sync(0xffffffffu, ps0, 1);
        ps0 += __shfl_xor_sync(0xffffffffu, ps0, 2);
        ps1 += __shfl_xor_sync(0xffffffffu, ps1, 1);
        ps1 += __shfl_xor_sync(0xffffffffu, ps1, 2);
        l0 = l0 * a0 + ps0;
        l1 = l1 * a1 + ps1;

        // rescale O
#pragma unroll
        for (int nt = 0; nt < 8; nt++) {
            o[nt][0] *= a0; o[nt][1] *= a0;
            o[nt][2] *= a1; o[nt][3] *= a1;
        }

        // O += P @ V   (P fragments via warp shuffles from score fragments)
#pragma unroll
        for (int kb2 = 0; kb2 < 8; kb2++) {
            unsigned c0 = __float_as_uint(s[kb2][0]);
            unsigned c1 = __float_as_uint(s[kb2][1]);
            unsigned c2 = __float_as_uint(s[kb2][2]);
            unsigned c3 = __float_as_uint(s[kb2][3]);
            unsigned e0 = __shfl_sync(0xffffffffu, c0, srcA);
            unsigned e1 = __shfl_sync(0xffffffffu, c1, srcA);
            unsigned e2 = __shfl_sync(0xffffffffu, c2, srcA);
            unsigned e3 = __shfl_sync(0xffffffffu, c3, srcA);
            unsigned f0 = __shfl_sync(0xffffffffu, c0, srcB);
            unsigned f1 = __shfl_sync(0xffffffffu, c1, srcB);
            unsigned f2 = __shfl_sync(0xffffffffu, c2, srcB);
            unsigned f3 = __shfl_sync(0xffffffffu, c3, srcB);
            unsigned af[4];
            af[0] = odd ? e1 : e0;
            af[1] = odd ? e3 : e2;
            af[2] = odd ? f1 : f0;
            af[3] = odd ? f3 : f2;
#pragma unroll
            for (int nt = 0; nt < 8; nt++) {
                unsigned bfr[2] = { __float_as_uint(Vs[kb2 * 8 + t4][nt * 8 + g]),
                                    __float_as_uint(Vs[kb2 * 8 + t4 + 4][nt * 8 + g]) };
                mma8(o[nt], af, bfr);
            }
        }
        __syncthreads();
    }

    // finalize
    float il0 = 1.0f / l0, il1 = 1.0f / l1;
    int r0 = q0 + wid * 16 + g;
    size_t g0 = (size_t)(b * S_LEN + r0) * D_MODEL + h * D_K;
    size_t g1 = (size_t)(b * S_LEN + r0 + 8) * D_MODEL + h * D_K;
#pragma unroll
    for (int nt = 0; nt < 8; nt++) {
        float2 o0 = {o[nt][0] * il0, o[nt][1] * il0};
        float2 o1 = {o[nt][2] * il1, o[nt][3] * il1};
        *(float2*)(O + g0 + nt * 8 + 2 * t4) = o0;
        *(float2*)(O + g1 + nt * 8 + 2 * t4) = o1;
    }
}

// ---------------------------------------------------------------------------
// LayerNorm: one block per row of 768. 192 threads, one float4 each.
// ---------------------------------------------------------------------------
__global__ void __launch_bounds__(192)
layernorm_kernel(const float* __restrict__ in,
                 const float* __restrict__ gamma,
                 const float* __restrict__ beta,
                 float* __restrict__ out) {
    const int row = blockIdx.x;
    const int tid = threadIdx.x;
    const float* x = in + (size_t)row * D_MODEL;
    float* y = out + (size_t)row * D_MODEL;

    float4 v = *(const float4*)(x + tid * 4);
    float s  = v.x + v.y + v.z + v.w;
    float sq = v.x * v.x + v.y * v.y + v.z * v.z + v.w * v.w;
#pragma unroll
    for (int off = 16; off > 0; off >>= 1) {
        s  += __shfl_xor_sync(0xffffffffu, s,  off);
        sq += __shfl_xor_sync(0xffffffffu, sq, off);
    }
    __shared__ float ss[6], ssq[6];
    int wid = tid >> 5, lane = tid & 31;
    if (lane == 0) { ss[wid] = s; ssq[wid] = sq; }
    __syncthreads();
    s = 0.0f; sq = 0.0f;
#pragma unroll
    for (int w = 0; w < 6; w++) { s += ss[w]; sq += ssq[w]; }

    const float inv_n = 1.0f / (float)D_MODEL;
    float mean = s * inv_n;
    float var  = sq * inv_n - mean * mean;
    float rstd = rsqrtf(var + 1e-5f);

    float4 gm = *(const float4*)(gamma + tid * 4);
    float4 bt = *(const float4*)(beta + tid * 4);
    float4 o;
    o.x = (v.x - mean) * rstd * gm.x + bt.x;
    o.y = (v.y - mean) * rstd * gm.y + bt.y;
    o.z = (v.z - mean) * rstd * gm.z + bt.z;
    o.w = (v.w - mean) * rstd * gm.w + bt.w;
    *(float4*)(y + tid * 4) = o;
}

// ---------------------------------------------------------------------------
// Launch
// ---------------------------------------------------------------------------
extern "C" void kernel_launch(void* const* d_in, const int* in_sizes, int n_in,
                              void* d_out, int out_size) {
    const float* x    = (const float*)d_in[0];
    const int*   mask = (const int*)  d_in[1];
    const float* wq = (const float*)d_in[2];
    const float* bq = (const float*)d_in[3];
    const float* wk = (const float*)d_in[4];
    const float* bk = (const float*)d_in[5];
    const float* wv = (const float*)d_in[6];
    const float* bv = (const float*)d_in[7];
    const float* wo = (const float*)d_in[8];
    const float* bo = (const float*)d_in[9];
    const float* w1 = (const float*)d_in[10];
    const float* b1 = (const float*)d_in[11];
    const float* w2 = (const float*)d_in[12];
    const float* b2 = (const float*)d_in[13];
    const float* g1 = (const float*)d_in[14];
    const float* be1= (const float*)d_in[15];
    const float* g2 = (const float*)d_in[16];
    const float* be2= (const float*)d_in[17];
    float* out = (float*)d_out;

    void* sptr = nullptr;
    cudaGetSymbolAddress(&sptr, g_scratch);
    float* S = (float*)sptr;
    float* q_b = S + OFF_Q;
    float* k_b = S + OFF_K;
    float* v_b = S + OFF_V;
    float* ctx = S + OFF_CTX;
    float* h1  = S + OFF_H1;
    float* x1  = S + OFF_X1;
    float* h2  = S + OFF_H2;
    float* ff  = S + OFF_FF;

    // allow 70 KB dynamic smem for the GEMM kernels (idempotent)
    cudaFuncSetAttribute(gemm_qkv,   cudaFuncAttributeMaxDynamicSharedMemorySize, GEMM_SMEM_BYTES);
    cudaFuncSetAttribute(gemm_tc<1>, cudaFuncAttributeMaxDynamicSharedMemorySize, GEMM_SMEM_BYTES);
    cudaFuncSetAttribute(gemm_tc<2>, cudaFuncAttributeMaxDynamicSharedMemorySize, GEMM_SMEM_BYTES);

    dim3 blk(256);
    dim3 grid_qkv(18, M_ROWS / 128);             // (18, 32) = 576 blocks
    dim3 grid_dm(D_MODEL / 128, M_ROWS / 128);   // (6, 32)
    dim3 grid_ff(D_FF / 128,   M_ROWS / 128);    // (24, 32)

    gemm_qkv<<<grid_qkv, blk, GEMM_SMEM_BYTES>>>(x, wq, wk, wv, bq, bk, bv,
                                                 q_b, k_b, v_b, M_ROWS, D_MODEL);

    dim3 agrid(S_LEN / BQ, B_SZ * N_HEADS);      // (16, 24)
    attn_tc2<<<agrid, blk>>>(q_b, k_b, v_b, mask, ctx);

    gemm_tc<2><<<grid_dm, blk, GEMM_SMEM_BYTES>>>(ctx, wo, bo, x, h1,
                                                  M_ROWS, D_MODEL, D_MODEL);
    layernorm_kernel<<<M_ROWS, 192>>>(h1, g1, be1, x1);

    gemm_tc<1><<<grid_ff, blk, GEMM_SMEM_BYTES>>>(x1, w1, b1, nullptr, ff,
                                                  M_ROWS, D_FF, D_MODEL);
    gemm_tc<2><<<grid_dm, blk, GEMM_SMEM_BYTES>>>(ff, w2, b2, x1, h2,
                                                  M_ROWS, D_MODEL, D_FF);
    layernorm_kernel<<<M_ROWS, 192>>>(h2, g2, be2, out);
}

// round 10
// speedup vs baseline: 4.0864x; 1.0633x over previous
#include <cuda_runtime.h>
#include <math.h>

// ---------------------------------------------------------------------------
// B=2, S=2048, D=768, H=12, dk=64, FF=3072
// ---------------------------------------------------------------------------
#define B_SZ     2
#define S_LEN    2048
#define D_MODEL  768
#define N_HEADS  12
#define D_K      64
#define D_FF     3072
#define M_ROWS   (B_SZ * S_LEN)           // 4096

#define SZ_DM   (M_ROWS * D_MODEL)
#define SZ_FF   (M_ROWS * D_FF)
__device__ float g_scratch[7 * SZ_DM + SZ_FF];

#define OFF_Q    (0 * SZ_DM)
#define OFF_K    (1 * SZ_DM)
#define OFF_V    (2 * SZ_DM)
#define OFF_CTX  (3 * SZ_DM)
#define OFF_H1   (4 * SZ_DM)
#define OFF_X1   (5 * SZ_DM)
#define OFF_H2   (6 * SZ_DM)
#define OFF_FF   (7 * SZ_DM)

// ---------------------------------------------------------------------------
// helpers: raw fp32 bits fed to mma.tf32 (HW truncates to tf32 — no cvt)
// ---------------------------------------------------------------------------
__device__ __forceinline__ unsigned smem_u32(const void* p) {
    return (unsigned)__cvta_generic_to_shared(p);
}
#define CP16(dst_u32, src_ptr) \
    asm volatile("cp.async.cg.shared.global [%0], [%1], 16;\n" :: "r"(dst_u32), "l"(src_ptr))
#define CP_COMMIT() asm volatile("cp.async.commit_group;\n")
#define CP_WAIT0()  asm volatile("cp.async.wait_group 0;\n")

__device__ __forceinline__ void mma8(float c[4], const unsigned a[4], const unsigned b[2]) {
    asm volatile(
        "mma.sync.aligned.m16n8k8.row.col.f32.tf32.tf32.f32 "
        "{%0,%1,%2,%3}, {%4,%5,%6,%7}, {%8,%9}, {%0,%1,%2,%3};\n"
        : "+f"(c[0]), "+f"(c[1]), "+f"(c[2]), "+f"(c[3])
        : "r"(a[0]), "r"(a[1]), "r"(a[2]), "r"(a[3]), "r"(b[0]), "r"(b[1]));
}

__device__ __forceinline__ float gelu_exact(float x) {
    return 0.5f * x * (1.0f + erff(x * 0.70710678118654752440f));
}

// ---------------------------------------------------------------------------
// GEMM: C[M,N] = A[M,K] @ W[K,N] + bias (+gelu / +residual)
// Block tile 128x128, BK=32, 256 threads (8 warps, 4m x 2n), warp tile 32x64.
// cp.async double-buffered DYNAMIC smem; one barrier per 32-K tile.
// ---------------------------------------------------------------------------
#define GEMM_SMEM_FLOATS (2 * 128 * 36 + 2 * 32 * 136)
#define GEMM_SMEM_BYTES  (GEMM_SMEM_FLOATS * 4)

template <int MODE>   // 0: bias, 1: bias+gelu, 2: bias+residual
__device__ __forceinline__ void gemm_body(
        const float* __restrict__ A, const float* __restrict__ W,
        const float* __restrict__ bias, const float* __restrict__ Res,
        float* __restrict__ C, int M, int N, int K, int bxi, int byi) {
    extern __shared__ __align__(16) float smem_dyn[];
    float* As = smem_dyn;                      // [2][128][36]
    float* Bs = smem_dyn + 2 * 128 * 36;       // [2][32][136]
#define AS(s, r, c) As[((s) * 128 + (r)) * 36 + (c)]
#define BS(s, r, c) Bs[((s) * 32 + (r)) * 136 + (c)]

    const int tid  = threadIdx.x;
    const int wid  = tid >> 5;
    const int lane = tid & 31;
    const int g    = lane >> 2;
    const int t4   = lane & 3;
    const int wm   = wid & 3;
    const int wn   = wid >> 2;
    const int bm   = byi * 128;
    const int bn   = bxi * 128;

    float c[2][8][4];
#pragma unroll
    for (int mt = 0; mt < 2; mt++)
#pragma unroll
        for (int nt = 0; nt < 8; nt++)
#pragma unroll
            for (int i = 0; i < 4; i++) c[mt][nt][i] = 0.0f;

    const int ar = tid >> 3, aq = tid & 7;     // A coords (row step 32)
    const int br = tid >> 5, bq = tid & 31;    // B coords (row step 8)

#define LOAD_TILE(stage, kbase)                                                  \
    do {                                                                         \
        _Pragma("unroll")                                                        \
        for (int i = 0; i < 4; i++) {                                            \
            int r = ar + i * 32;                                                 \
            CP16(smem_u32(&AS(stage, r, aq * 4)),                                \
                 A + (size_t)(bm + r) * K + (kbase) + aq * 4);                   \
        }                                                                        \
        _Pragma("unroll")                                                        \
        for (int i = 0; i < 4; i++) {                                            \
            int r = br + i * 8;                                                  \
            CP16(smem_u32(&BS(stage, r, bq * 4)),                                \
                 W + (size_t)((kbase) + r) * N + bn + bq * 4);                   \
        }                                                                        \
        CP_COMMIT();                                                             \
    } while (0)

    LOAD_TILE(0, 0);
    CP_WAIT0();
    __syncthreads();

    int buf = 0;
    for (int k0 = 0; k0 < K; k0 += 32) {
        const bool has_next = (k0 + 32) < K;
        if (has_next) LOAD_TILE(buf ^ 1, k0 + 32);

#pragma unroll
        for (int kb = 0; kb < 4; kb++) {
            const int kk = kb * 8;
            unsigned a[2][4], b[8][2];
#pragma unroll
            for (int mt = 0; mt < 2; mt++) {
                int r = wm * 32 + mt * 16 + g;
                a[mt][0] = __float_as_uint(AS(buf, r,     kk + t4));
                a[mt][1] = __float_as_uint(AS(buf, r + 8, kk + t4));
                a[mt][2] = __float_as_uint(AS(buf, r,     kk + t4 + 4));
                a[mt][3] = __float_as_uint(AS(buf, r + 8, kk + t4 + 4));
            }
#pragma unroll
            for (int nt = 0; nt < 8; nt++) {
                int cb = wn * 64 + nt * 8;
                b[nt][0] = __float_as_uint(BS(buf, kk + t4,     cb + g));
                b[nt][1] = __float_as_uint(BS(buf, kk + t4 + 4, cb + g));
            }
#pragma unroll
            for (int mt = 0; mt < 2; mt++)
#pragma unroll
                for (int nt = 0; nt < 8; nt++)
                    mma8(c[mt][nt], a[mt], b[nt]);
        }

        if (has_next) CP_WAIT0();
        __syncthreads();
        buf ^= 1;
    }

    // epilogue
#pragma unroll
    for (int mt = 0; mt < 2; mt++) {
        int r0 = bm + wm * 32 + mt * 16 + g;
        int r1 = r0 + 8;
#pragma unroll
        for (int nt = 0; nt < 8; nt++) {
            int col = bn + wn * 64 + nt * 8 + t4 * 2;
            float bb0 = bias[col], bb1 = bias[col + 1];
            float v00 = c[mt][nt][0] + bb0;
            float v01 = c[mt][nt][1] + bb1;
            float v10 = c[mt][nt][2] + bb0;
            float v11 = c[mt][nt][3] + bb1;
            if (MODE == 1) {
                v00 = gelu_exact(v00); v01 = gelu_exact(v01);
                v10 = gelu_exact(v10); v11 = gelu_exact(v11);
            }
            if (MODE == 2) {
                float2 r0v = *(const float2*)(Res + (size_t)r0 * N + col);
                float2 r1v = *(const float2*)(Res + (size_t)r1 * N + col);
                v00 += r0v.x; v01 += r0v.y; v10 += r1v.x; v11 += r1v.y;
            }
            float2 o0 = {v00, v01}, o1 = {v10, v11};
            *(float2*)(C + (size_t)r0 * N + col) = o0;
            *(float2*)(C + (size_t)r1 * N + col) = o1;
        }
    }
#undef AS
#undef BS
}

template <int MODE>
__global__ void __launch_bounds__(256)
gemm_tc(const float* __restrict__ A, const float* __restrict__ W,
        const float* __restrict__ bias, const float* __restrict__ Res,
        float* __restrict__ C, int M, int N, int K) {
    gemm_body<MODE>(A, W, bias, Res, C, M, N, K, blockIdx.x, blockIdx.y);
}

// Fused QKV: grid.x = 18 (6 col-blocks per projection), selects W/bias/output.
__global__ void __launch_bounds__(256)
gemm_qkv(const float* __restrict__ A,
         const float* __restrict__ Wq, const float* __restrict__ Wk, const float* __restrict__ Wv,
         const float* __restrict__ bq, const float* __restrict__ bk, const float* __restrict__ bv,
         float* __restrict__ Oq, float* __restrict__ Ok, float* __restrict__ Ov,
         int M, int K) {
    int sel = blockIdx.x / 6;
    int bx  = blockIdx.x - sel * 6;
    const float* W    = (sel == 0) ? Wq : (sel == 1) ? Wk : Wv;
    const float* bias = (sel == 0) ? bq : (sel == 1) ? bk : bv;
    float*       C    = (sel == 0) ? Oq : (sel == 1) ? Ok : Ov;
    gemm_body<0>(A, W, bias, nullptr, C, M, D_MODEL, K, bx, blockIdx.y);
}

// ---------------------------------------------------------------------------
// Flash attention v3 (fixed): BQ=128 (16 q-rows/warp, 8 warps), BKV=64.
// Double-buffered cp.async K/V/mask pipeline — next tile's copies fly under
// the current tile's mma+softmax. One barrier per tile. K stored plain
// (B-frags = 2x conflict-free LDS.32). Q fragments resident in registers;
// register softmax; P->A-fragment via warp shuffles.
// FULL tile coverage: each thread copies 4x16B of K and 4x16B of V.
// ---------------------------------------------------------------------------
#define BQ  128
#define BKV 64

__global__ void __launch_bounds__(256, 3)
attn_tc3(const float* __restrict__ Q, const float* __restrict__ K,
         const float* __restrict__ V, const int* __restrict__ mask,
         float* __restrict__ O) {
    __shared__ __align__(16) float Ks[2][64][68];   // [stage][kv][d]
    __shared__ __align__(16) float Vs[2][64][68];   // [stage][kv][d]
    __shared__ __align__(16) int   Ms[2][64];       // [stage][kv] mask ints

    const int bh   = blockIdx.y;
    const int b    = bh / N_HEADS;
    const int h    = bh % N_HEADS;
    const int q0   = blockIdx.x * BQ;
    const int tid  = threadIdx.x;
    const int wid  = tid >> 5;
    const int lane = tid & 31;
    const int g    = lane >> 2;
    const int t4   = lane & 3;

    const float* Qb = Q + (size_t)b * S_LEN * D_MODEL + h * D_K;
    const float* Kb = K + (size_t)b * S_LEN * D_MODEL + h * D_K;
    const float* Vb = V + (size_t)b * S_LEN * D_MODEL + h * D_K;
    const int*   mb = mask + b * S_LEN;

    // ---- stage Q (128 x 64) through Ks[0]/Vs[0], then into registers ----
#pragma unroll
    for (int i = 0; i < 8; i++) {
        int f = tid + i * 256;
        int r = f >> 4, dq = f & 15;
        float4 v = *(const float4*)(Qb + (size_t)(q0 + r) * D_MODEL + dq * 4);
        if (r < 64) *(float4*)&Ks[0][r][dq * 4]      = v;
        else        *(float4*)&Vs[0][r - 64][dq * 4] = v;
    }
    __syncthreads();

    unsigned qf[8][4];
    {
        int r0 = wid * 16 + g;
        int r1 = r0 + 8;
        const float* row0 = (r0 < 64) ? &Ks[0][r0][0] : &Vs[0][r0 - 64][0];
        const float* row1 = (r1 < 64) ? &Ks[0][r1][0] : &Vs[0][r1 - 64][0];
#pragma unroll
        for (int kb = 0; kb < 8; kb++) {
            qf[kb][0] = __float_as_uint(row0[kb * 8 + t4]);
            qf[kb][1] = __float_as_uint(row1[kb * 8 + t4]);
            qf[kb][2] = __float_as_uint(row0[kb * 8 + t4 + 4]);
            qf[kb][3] = __float_as_uint(row1[kb * 8 + t4 + 4]);
        }
    }
    __syncthreads();   // all qf read before tile 0 overwrites Ks[0]/Vs[0]

    // full tile copy: 1024 16B-chunks each for K and V -> 4+4 CP16 per thread
#define LOAD_KV(stage, kbase)                                                    \
    do {                                                                         \
        _Pragma("unroll")                                                        \
        for (int i = 0; i < 4; i++) {                                            \
            int f = tid + i * 256;                                               \
            int r = f >> 4, dq = f & 15;                                         \
            CP16(smem_u32(&Ks[stage][r][dq * 4]),                                \
                 Kb + (size_t)((kbase) + r) * D_MODEL + dq * 4);                 \
            CP16(smem_u32(&Vs[stage][r][dq * 4]),                                \
                 Vb + (size_t)((kbase) + r) * D_MODEL + dq * 4);                 \
        }                                                                        \
        if (tid < 16)                                                            \
            CP16(smem_u32(&Ms[stage][tid * 4]), mb + (kbase) + tid * 4);         \
        CP_COMMIT();                                                             \
    } while (0)

    float o[8][4];
#pragma unroll
    for (int nt = 0; nt < 8; nt++)
#pragma unroll
        for (int i = 0; i < 4; i++) o[nt][i] = 0.0f;
    float m0 = -1e30f, m1 = -1e30f, l0 = 0.0f, l1 = 0.0f;

    const int  srcA = (lane & 28) | (t4 >> 1);
    const int  srcB = srcA + 2;
    const bool odd  = (t4 & 1) != 0;

    LOAD_KV(0, 0);

    int buf = 0;
    for (int k0 = 0; k0 < S_LEN; k0 += BKV) {
        CP_WAIT0();          // tile k0 resident
        __syncthreads();     // visible to all; prior compute done with buf^1
        if (k0 + BKV < S_LEN) LOAD_KV(buf ^ 1, k0 + BKV);

        // S = Q @ K^T  (16 q-rows x 64 kv per warp)
        float s[8][4];
#pragma unroll
        for (int nb = 0; nb < 8; nb++) {
            s[nb][0] = 0.0f; s[nb][1] = 0.0f; s[nb][2] = 0.0f; s[nb][3] = 0.0f;
        }
#pragma unroll
        for (int kb = 0; kb < 8; kb++) {
#pragma unroll
            for (int nb = 0; nb < 8; nb++) {
                unsigned bfr[2] = {
                    __float_as_uint(Ks[buf][nb * 8 + g][kb * 8 + t4]),
                    __float_as_uint(Ks[buf][nb * 8 + g][kb * 8 + t4 + 4]) };
                mma8(s[nb], qf[kb], bfr);
            }
        }

        // mask + scale + row max
        float mx0 = -1e30f, mx1 = -1e30f;
#pragma unroll
        for (int nb = 0; nb < 8; nb++) {
            int2 mm = *(const int2*)&Ms[buf][nb * 8 + 2 * t4];
            float bx = mm.x ? 0.0f : -1e9f;
            float by = mm.y ? 0.0f : -1e9f;
            s[nb][0] = s[nb][0] * 0.125f + bx;
            s[nb][1] = s[nb][1] * 0.125f + by;
            s[nb][2] = s[nb][2] * 0.125f + bx;
            s[nb][3] = s[nb][3] * 0.125f + by;
            mx0 = fmaxf(mx0, fmaxf(s[nb][0], s[nb][1]));
            mx1 = fmaxf(mx1, fmaxf(s[nb][2], s[nb][3]));
        }
        mx0 = fmaxf(mx0, __shfl_xor_sync(0xffffffffu, mx0, 1));
        mx0 = fmaxf(mx0, __shfl_xor_sync(0xffffffffu, mx0, 2));
        mx1 = fmaxf(mx1, __shfl_xor_sync(0xffffffffu, mx1, 1));
        mx1 = fmaxf(mx1, __shfl_xor_sync(0xffffffffu, mx1, 2));

        float mn0 = fmaxf(m0, mx0), mn1 = fmaxf(m1, mx1);
        float a0 = __expf(m0 - mn0), a1 = __expf(m1 - mn1);
        m0 = mn0; m1 = mn1;

        float ps0 = 0.0f, ps1 = 0.0f;
#pragma unroll
        for (int nb = 0; nb < 8; nb++) {
            float p0 = __expf(s[nb][0] - mn0); ps0 += p0;
            float p1 = __expf(s[nb][1] - mn0); ps0 += p1;
            float p2 = __expf(s[nb][2] - mn1); ps1 += p2;
            float p3 = __expf(s[nb][3] - mn1); ps1 += p3;
            s[nb][0] = p0; s[nb][1] = p1; s[nb][2] = p2; s[nb][3] = p3;
        }
        ps0 += __shfl_xor_sync(0xffffffffu, ps0, 1);
        ps0 += __shfl_xor_sync(0xffffffffu, ps0, 2);
        ps1 += __shfl_xor_sync(0xffffffffu, ps1, 1);
        ps1 += __shfl_xor_sync(0xffffffffu, ps1, 2);
        l0 = l0 * a0 + ps0;
        l1 = l1 * a1 + ps1;

        // rescale O
#pragma unroll
        for (int nt = 0; nt < 8; nt++) {
            o[nt][0] *= a0; o[nt][1] *= a0;
            o[nt][2] *= a1; o[nt][3] *= a1;
        }

        // O += P @ V   (P fragments via warp shuffles from score fragments)
#pragma unroll
        for (int kb2 = 0; kb2 < 8; kb2++) {
            unsigned c0 = __float_as_uint(s[kb2][0]);
            unsigned c1 = __float_as_uint(s[kb2][1]);
            unsigned c2 = __float_as_uint(s[kb2][2]);
            unsigned c3 = __float_as_uint(s[kb2][3]);
            unsigned e0 = __shfl_sync(0xffffffffu, c0, srcA);
            unsigned e1 = __shfl_sync(0xffffffffu, c1, srcA);
            unsigned e2 = __shfl_sync(0xffffffffu, c2, srcA);
            unsigned e3 = __shfl_sync(0xffffffffu, c3, srcA);
            unsigned f0 = __shfl_sync(0xffffffffu, c0, srcB);
            unsigned f1 = __shfl_sync(0xffffffffu, c1, srcB);
            unsigned f2 = __shfl_sync(0xffffffffu, c2, srcB);
            unsigned f3 = __shfl_sync(0xffffffffu, c3, srcB);
            unsigned af[4];
            af[0] = odd ? e1 : e0;
            af[1] = odd ? e3 : e2;
            af[2] = odd ? f1 : f0;
            af[3] = odd ? f3 : f2;
#pragma unroll
            for (int nt = 0; nt < 8; nt++) {
                unsigned bfr[2] = {
                    __float_as_uint(Vs[buf][kb2 * 8 + t4][nt * 8 + g]),
                    __float_as_uint(Vs[buf][kb2 * 8 + t4 + 4][nt * 8 + g]) };
                mma8(o[nt], af, bfr);
            }
        }
        buf ^= 1;
    }

    // finalize
    float il0 = 1.0f / l0, il1 = 1.0f / l1;
    int r0 = q0 + wid * 16 + g;
    size_t g0 = (size_t)(b * S_LEN + r0) * D_MODEL + h * D_K;
    size_t g1 = (size_t)(b * S_LEN + r0 + 8) * D_MODEL + h * D_K;
#pragma unroll
    for (int nt = 0; nt < 8; nt++) {
        float2 o0 = {o[nt][0] * il0, o[nt][1] * il0};
        float2 o1 = {o[nt][2] * il1, o[nt][3] * il1};
        *(float2*)(O + g0 + nt * 8 + 2 * t4) = o0;
        *(float2*)(O + g1 + nt * 8 + 2 * t4) = o1;
    }
}

// ---------------------------------------------------------------------------
// LayerNorm: one block per row of 768. 192 threads, one float4 each.
// ---------------------------------------------------------------------------
__global__ void __launch_bounds__(192)
layernorm_kernel(const float* __restrict__ in,
                 const float* __restrict__ gamma,
                 const float* __restrict__ beta,
                 float* __restrict__ out) {
    const int row = blockIdx.x;
    const int tid = threadIdx.x;
    const float* x = in + (size_t)row * D_MODEL;
    float* y = out + (size_t)row * D_MODEL;

    float4 v = *(const float4*)(x + tid * 4);
    float s  = v.x + v.y + v.z + v.w;
    float sq = v.x * v.x + v.y * v.y + v.z * v.z + v.w * v.w;
#pragma unroll
    for (int off = 16; off > 0; off >>= 1) {
        s  += __shfl_xor_sync(0xffffffffu, s,  off);
        sq += __shfl_xor_sync(0xffffffffu, sq, off);
    }
    __shared__ float ss[6], ssq[6];
    int wid = tid >> 5, lane = tid & 31;
    if (lane == 0) { ss[wid] = s; ssq[wid] = sq; }
    __syncthreads();
    s = 0.0f; sq = 0.0f;
#pragma unroll
    for (int w = 0; w < 6; w++) { s += ss[w]; sq += ssq[w]; }

    const float inv_n = 1.0f / (float)D_MODEL;
    float mean = s * inv_n;
    float var  = sq * inv_n - mean * mean;
    float rstd = rsqrtf(var + 1e-5f);

    float4 gm = *(const float4*)(gamma + tid * 4);
    float4 bt = *(const float4*)(beta + tid * 4);
    float4 o;
    o.x = (v.x - mean) * rstd * gm.x + bt.x;
    o.y = (v.y - mean) * rstd * gm.y + bt.y;
    o.z = (v.z - mean) * rstd * gm.z + bt.z;
    o.w = (v.w - mean) * rstd * gm.w + bt.w;
    *(float4*)(y + tid * 4) = o;
}

// ---------------------------------------------------------------------------
// Launch
// ---------------------------------------------------------------------------
extern "C" void kernel_launch(void* const* d_in, const int* in_sizes, int n_in,
                              void* d_out, int out_size) {
    const float* x    = (const float*)d_in[0];
    const int*   mask = (const int*)  d_in[1];
    const float* wq = (const float*)d_in[2];
    const float* bq = (const float*)d_in[3];
    const float* wk = (const float*)d_in[4];
    const float* bk = (const float*)d_in[5];
    const float* wv = (const float*)d_in[6];
    const float* bv = (const float*)d_in[7];
    const float* wo = (const float*)d_in[8];
    const float* bo = (const float*)d_in[9];
    const float* w1 = (const float*)d_in[10];
    const float* b1 = (const float*)d_in[11];
    const float* w2 = (const float*)d_in[12];
    const float* b2 = (const float*)d_in[13];
    const float* g1 = (const float*)d_in[14];
    const float* be1= (const float*)d_in[15];
    const float* g2 = (const float*)d_in[16];
    const float* be2= (const float*)d_in[17];
    float* out = (float*)d_out;

    void* sptr = nullptr;
    cudaGetSymbolAddress(&sptr, g_scratch);
    float* S = (float*)sptr;
    float* q_b = S + OFF_Q;
    float* k_b = S + OFF_K;
    float* v_b = S + OFF_V;
    float* ctx = S + OFF_CTX;
    float* h1  = S + OFF_H1;
    float* x1  = S + OFF_X1;
    float* h2  = S + OFF_H2;
    float* ff  = S + OFF_FF;

    cudaFuncSetAttribute(gemm_qkv,   cudaFuncAttributeMaxDynamicSharedMemorySize, GEMM_SMEM_BYTES);
    cudaFuncSetAttribute(gemm_tc<1>, cudaFuncAttributeMaxDynamicSharedMemorySize, GEMM_SMEM_BYTES);
    cudaFuncSetAttribute(gemm_tc<2>, cudaFuncAttributeMaxDynamicSharedMemorySize, GEMM_SMEM_BYTES);

    dim3 blk(256);
    dim3 grid_qkv(18, M_ROWS / 128);             // (18, 32) = 576 blocks
    dim3 grid_dm(D_MODEL / 128, M_ROWS / 128);   // (6, 32)
    dim3 grid_ff(D_FF / 128,   M_ROWS / 128);    // (24, 32)

    gemm_qkv<<<grid_qkv, blk, GEMM_SMEM_BYTES>>>(x, wq, wk, wv, bq, bk, bv,
                                                 q_b, k_b, v_b, M_ROWS, D_MODEL);

    dim3 agrid(S_LEN / BQ, B_SZ * N_HEADS);      // (16, 24)
    attn_tc3<<<agrid, blk>>>(q_b, k_b, v_b, mask, ctx);

    gemm_tc<2><<<grid_dm, blk, GEMM_SMEM_BYTES>>>(ctx, wo, bo, x, h1,
                                                  M_ROWS, D_MODEL, D_MODEL);
    layernorm_kernel<<<M_ROWS, 192>>>(h1, g1, be1, x1);

    gemm_tc<1><<<grid_ff, blk, GEMM_SMEM_BYTES>>>(x1, w1, b1, nullptr, ff,
                                                  M_ROWS, D_FF, D_MODEL);
    gemm_tc<2><<<grid_dm, blk, GEMM_SMEM_BYTES>>>(ff, w2, b2, x1, h2,
                                                  M_ROWS, D_MODEL, D_FF);
    layernorm_kernel<<<M_ROWS, 192>>>(h2, g2, be2, out);
}